// round 10
// baseline (speedup 1.0000x reference)
#include <cuda_runtime.h>
#include <cuda_bf16.h>
#include <math.h>
#include <cstdint>

// Problem constants
#define BATCH 2
#define TSEQ  2048
#define CDIM  1024
#define NH    16
#define HD    64
#define THREEC (3*CDIM)
#define MROWS (BATCH*TSEQ)   // 4096
#define K2    (2*CDIM)       // [hi|lo] packed K = 2048

// ---------------------------------------------------------------------------
// Scratch (__device__ globals; allocation-free rule)
// ---------------------------------------------------------------------------
__device__ __nv_bfloat16 g_ahat[(size_t)MROWS * K2];       // packed activations
__device__ __nv_bfloat16 g_bqkv[(size_t)THREEC * K2];      // packed Wqkv^T
__device__ __nv_bfloat16 g_bproj[(size_t)CDIM * K2];       // packed Wproj^T
// Pre-split attention operands (written directly by the QKV GEMM epilogue)
__device__ __nv_bfloat16 g_qpack[(size_t)BATCH * NH * TSEQ * 128];
__device__ __nv_bfloat16 g_kpack[(size_t)BATCH * NH * TSEQ * 128];
__device__ __nv_bfloat16 g_vpack[(size_t)BATCH * NH * HD * 2 * TSEQ];

// ---------------------------------------------------------------------------
// Helpers (base-ISA only: cp.async / ldmatrix / mma.sync)
// ---------------------------------------------------------------------------
__device__ __forceinline__ uint32_t smem_u32(const void* p) {
    uint32_t a;
    asm("{ .reg .u64 t; cvta.to.shared.u64 t, %1; cvt.u32.u64 %0, t; }"
        : "=r"(a) : "l"(p));
    return a;
}
#define CP_ASYNC16(smaddr, gptr) \
    asm volatile("cp.async.cg.shared.global [%0], [%1], 16;" \
                 :: "r"(smaddr), "l"(gptr))
#define CP_COMMIT() asm volatile("cp.async.commit_group;" ::: "memory")
#define CP_WAIT(n)  asm volatile("cp.async.wait_group %0;" :: "n"(n) : "memory")

#define LDSM_X4(r0, r1, r2, r3, addr) \
    asm volatile("ldmatrix.sync.aligned.m8n8.x4.shared.b16 {%0,%1,%2,%3}, [%4];" \
                 : "=r"(r0), "=r"(r1), "=r"(r2), "=r"(r3) : "r"(addr))

#define MMA_BF16(c0, c1, c2, c3, a0, a1, a2, a3, b0, b1) \
    asm volatile("mma.sync.aligned.m16n8k16.row.col.f32.bf16.bf16.f32 " \
                 "{%0,%1,%2,%3}, {%4,%5,%6,%7}, {%8,%9}, {%0,%1,%2,%3};" \
                 : "+f"(c0), "+f"(c1), "+f"(c2), "+f"(c3) \
                 : "r"(a0), "r"(a1), "r"(a2), "r"(a3), "r"(b0), "r"(b1))

__device__ __forceinline__ uint32_t pack_bf16(float x, float y) {
    __nv_bfloat162 h = __floats2bfloat162_rn(x, y);
    return *reinterpret_cast<uint32_t*>(&h);
}

// ---------------------------------------------------------------------------
// Split-convert activations: A[M,K] fp32 -> Ahat[M,2K] bf16 = [hi | lo]
// ---------------------------------------------------------------------------
__global__ void convert_split_act(const float* __restrict__ in,
                                  __nv_bfloat16* __restrict__ out, int MK, int K)
{
    int idx = blockIdx.x * blockDim.x + threadIdx.x;
    if (idx >= MK) return;
    int m = idx / K, k = idx - m * K;
    float v = in[idx];
    __nv_bfloat16 hi = __float2bfloat16(v);
    __nv_bfloat16 lo = __float2bfloat16(v - __bfloat162float(hi));
    size_t base = (size_t)m * (2 * K);
    out[base + k]     = hi;
    out[base + K + k] = lo;
}

// ---------------------------------------------------------------------------
// Transpose + split-convert weights: W[K,N] fp32 -> Bhat[N,2K] bf16 = [hi|lo]
// ---------------------------------------------------------------------------
__global__ void convert_split_wT(const float* __restrict__ W,
                                 __nv_bfloat16* __restrict__ out, int K, int N)
{
    __shared__ float t[32][33];
    const int tx = threadIdx.x, ty = threadIdx.y;   // block (32, 8)
    const int n0 = blockIdx.x * 32, k0 = blockIdx.y * 32;
    #pragma unroll
    for (int j = 0; j < 4; j++)
        t[ty + j * 8][tx] = W[(size_t)(k0 + ty + j * 8) * N + n0 + tx];
    __syncthreads();
    #pragma unroll
    for (int j = 0; j < 4; j++) {
        const int nn = ty + j * 8;
        float v = t[tx][nn];
        __nv_bfloat16 hi = __float2bfloat16(v);
        __nv_bfloat16 lo = __float2bfloat16(v - __bfloat162float(hi));
        size_t base = (size_t)(n0 + nn) * (2 * K) + k0 + tx;
        out[base]     = hi;
        out[base + K] = lo;
    }
}

// ---------------------------------------------------------------------------
// Shared GEMM mainloop config: 128x128 CTA tile, 4 warps (128 thr),
// 64x64 warp tile. [hi|lo] operands + register 3-term split.
// ---------------------------------------------------------------------------
#define GBK   32
#define NSTG  (CDIM / GBK)            // 32
#define ROWB  144
#define STAGE_BYTES (128 * ROWB)      // 18432
#define STAGES 2
#define GEMM_SMEM (2 * STAGES * STAGE_BYTES)   // 73728 bytes
#define GEMM_THREADS 128

// Mainloop macro body. Defines acc[4][8][4] and runs the full K loop.
#define GEMM_MAINLOOP(Aptr, Bptr)                                              \
    extern __shared__ __align__(16) unsigned char gsm[];                       \
    const int tid  = threadIdx.x;                                              \
    const int wid  = tid >> 5;                                                 \
    const int lane = tid & 31;                                                 \
    const int wm   = wid & 1;                                                  \
    const int wn   = wid >> 1;                                                 \
    const int row0 = blockIdx.y * 128;                                         \
    const int col0 = blockIdx.x * 128;                                         \
    const uint32_t smA_b = smem_u32(gsm);                                      \
    const uint32_t smB_b = smA_b + STAGES * STAGE_BYTES;                       \
    const __nv_bfloat16* Arow = (Aptr) + (size_t)row0 * K2;                    \
    const __nv_bfloat16* Brow = (Bptr) + (size_t)col0 * K2;                    \
    auto load_stage = [&](int s, int buf) {                                    \
        const int k0 = s * GBK;                                                \
        const uint32_t ao = smA_b + buf * STAGE_BYTES;                         \
        const uint32_t bo = smB_b + buf * STAGE_BYTES;                         \
        _Pragma("unroll")                                                      \
        for (int i = 0; i < 8; i++) {                                          \
            const int idx = i * GEMM_THREADS + tid;                            \
            const int r   = idx >> 3;                                          \
            const int c   = idx & 7;                                           \
            const int cc  = c & 3;                                             \
            const int gofs = (c < 4) ? (k0 + cc * 8) : (CDIM + k0 + cc * 8);   \
            const uint32_t so = (uint32_t)(r * ROWB + cc * 16 + ((c < 4) ? 0 : 64)); \
            CP_ASYNC16(ao + so, Arow + (size_t)r * K2 + gofs);                 \
            CP_ASYNC16(bo + so, Brow + (size_t)r * K2 + gofs);                 \
        }                                                                      \
    };                                                                         \
    float acc[4][8][4];                                                        \
    _Pragma("unroll")                                                          \
    for (int i = 0; i < 4; i++)                                                \
        _Pragma("unroll")                                                      \
        for (int j = 0; j < 8; j++)                                            \
            _Pragma("unroll")                                                  \
            for (int k = 0; k < 4; k++) acc[i][j][k] = 0.f;                    \
    const int lrow = lane & 15;                                                \
    const int lcol = (lane >> 4) << 4;                                         \
    load_stage(0, 0);                                                          \
    CP_COMMIT();                                                               \
    for (int s = 0; s < NSTG; s++) {                                           \
        CP_WAIT(0);                                                            \
        __syncthreads();                                                       \
        if (s + 1 < NSTG) { load_stage(s + 1, (s + 1) & 1); CP_COMMIT(); }     \
        const int buf = s & 1;                                                 \
        const uint32_t aB = smA_b + buf * STAGE_BYTES;                         \
        const uint32_t bB = smB_b + buf * STAGE_BYTES;                         \
        _Pragma("unroll")                                                      \
        for (int ks = 0; ks < 2; ks++) {                                       \
            uint32_t ahi[4][4], alo[4][4], bhi[4][4], blo[4][4];               \
            _Pragma("unroll")                                                  \
            for (int fm = 0; fm < 4; fm++) {                                   \
                const uint32_t ad = aB +                                       \
                    (uint32_t)((wm * 64 + fm * 16 + lrow) * ROWB + ks * 32) + lcol; \
                LDSM_X4(ahi[fm][0], ahi[fm][1], ahi[fm][2], ahi[fm][3], ad);   \
                LDSM_X4(alo[fm][0], alo[fm][1], alo[fm][2], alo[fm][3], ad + 64); \
            }                                                                  \
            _Pragma("unroll")                                                  \
            for (int g = 0; g < 4; g++) {                                      \
                const uint32_t bd = bB +                                       \
                    (uint32_t)((wn * 64 + g * 16 + lrow) * ROWB + ks * 32) + lcol; \
                LDSM_X4(bhi[g][0], bhi[g][1], bhi[g][2], bhi[g][3], bd);       \
                LDSM_X4(blo[g][0], blo[g][1], blo[g][2], blo[g][3], bd + 64);  \
            }                                                                  \
            _Pragma("unroll")                                                  \
            for (int fm = 0; fm < 4; fm++)                                     \
                _Pragma("unroll")                                              \
                for (int fn = 0; fn < 8; fn++) {                               \
                    const int g = fn >> 1, h = fn & 1;                         \
                    MMA_BF16(acc[fm][fn][0], acc[fm][fn][1],                   \
                             acc[fm][fn][2], acc[fm][fn][3],                   \
                             ahi[fm][0], ahi[fm][1], ahi[fm][2], ahi[fm][3],   \
                             bhi[g][h], bhi[g][2 + h]);                        \
                    MMA_BF16(acc[fm][fn][0], acc[fm][fn][1],                   \
                             acc[fm][fn][2], acc[fm][fn][3],                   \
                             ahi[fm][0], ahi[fm][1], ahi[fm][2], ahi[fm][3],   \
                             blo[g][h], blo[g][2 + h]);                        \
                    MMA_BF16(acc[fm][fn][0], acc[fm][fn][1],                   \
                             acc[fm][fn][2], acc[fm][fn][3],                   \
                             alo[fm][0], alo[fm][1], alo[fm][2], alo[fm][3],   \
                             bhi[g][h], bhi[g][2 + h]);                        \
                }                                                              \
        }                                                                      \
    }

// ---------------------------------------------------------------------------
// Proj GEMM: plain fp32 output + bias
// ---------------------------------------------------------------------------
__global__ __launch_bounds__(GEMM_THREADS) void gemm_mma(
    const __nv_bfloat16* __restrict__ A,
    const __nv_bfloat16* __restrict__ B,
    const float* __restrict__ bias,
    float* __restrict__ C, int M, int N)
{
    GEMM_MAINLOOP(A, B)

    const int erow = lane >> 2;
    const int ecol = (lane & 3) << 1;
    #pragma unroll
    for (int fm = 0; fm < 4; fm++) {
        const int r0g = row0 + wm * 64 + fm * 16 + erow;
        #pragma unroll
        for (int fn = 0; fn < 8; fn++) {
            const int cg = col0 + wn * 64 + fn * 8 + ecol;
            const float b0 = bias[cg], b1 = bias[cg + 1];
            float2 v0 = make_float2(acc[fm][fn][0] + b0, acc[fm][fn][1] + b1);
            float2 v1 = make_float2(acc[fm][fn][2] + b0, acc[fm][fn][3] + b1);
            *reinterpret_cast<float2*>(&C[(size_t)r0g * N + cg]) = v0;
            *reinterpret_cast<float2*>(&C[(size_t)(r0g + 8) * N + cg]) = v1;
        }
    }
}

// ---------------------------------------------------------------------------
// QKV GEMM with fused pack epilogue (writes qpack/kpack/vpack directly)
// ---------------------------------------------------------------------------
__global__ __launch_bounds__(GEMM_THREADS) void gemm_qkv(
    const __nv_bfloat16* __restrict__ A,
    const __nv_bfloat16* __restrict__ B,
    const float* __restrict__ bias,
    __nv_bfloat16* __restrict__ qpack,
    __nv_bfloat16* __restrict__ kpack,
    __nv_bfloat16* __restrict__ vpack)
{
    GEMM_MAINLOOP(A, B)

    const int erow = lane >> 2;
    const int ecol = (lane & 3) << 1;
    const int sec  = col0 >> 10;                      // 0=Q 1=K 2=V
    const int hh   = ((col0 & 1023) >> 6) + wn;       // head (per-warp constant)
    const float scale = (sec == 0) ? 0.125f : 1.0f;

    #pragma unroll
    for (int fm = 0; fm < 4; fm++) {
        const int t0g = row0 + wm * 64 + fm * 16 + erow;
        const int bidx = t0g >> 11;
        const int bh   = bidx * NH + hh;
        const int tl0  = t0g & 2047;
        const int tl1  = tl0 + 8;
        #pragma unroll
        for (int fn = 0; fn < 8; fn++) {
            const int cg = col0 + wn * 64 + fn * 8 + ecol;
            const int d  = (cg & 63);
            const float b0 = bias[cg], b1 = bias[cg + 1];
            const float v00 = (acc[fm][fn][0] + b0) * scale;
            const float v01 = (acc[fm][fn][1] + b1) * scale;
            const float v10 = (acc[fm][fn][2] + b0) * scale;
            const float v11 = (acc[fm][fn][3] + b1) * scale;

            const uint32_t h0 = pack_bf16(v00, v01);
            const uint32_t h1 = pack_bf16(v10, v11);
            const __nv_bfloat162 h0b = *reinterpret_cast<const __nv_bfloat162*>(&h0);
            const __nv_bfloat162 h1b = *reinterpret_cast<const __nv_bfloat162*>(&h1);
            const uint32_t l0 = pack_bf16(v00 - __bfloat162float(h0b.x),
                                          v01 - __bfloat162float(h0b.y));
            const uint32_t l1 = pack_bf16(v10 - __bfloat162float(h1b.x),
                                          v11 - __bfloat162float(h1b.y));

            if (sec < 2) {
                __nv_bfloat16* dst = (sec == 0) ? qpack : kpack;
                const size_t r0 = ((size_t)bh * TSEQ + tl0) * 128 + d;
                const size_t r1 = ((size_t)bh * TSEQ + tl1) * 128 + d;
                *reinterpret_cast<uint32_t*>(&dst[r0])      = h0;
                *reinterpret_cast<uint32_t*>(&dst[r0 + 64]) = l0;
                *reinterpret_cast<uint32_t*>(&dst[r1])      = h1;
                *reinterpret_cast<uint32_t*>(&dst[r1 + 64]) = l1;
            } else {
                #pragma unroll
                for (int dd = 0; dd < 2; dd++) {
                    const size_t vb = ((size_t)bh * HD + d + dd) * (2 * TSEQ);
                    const size_t c0 = vb + (tl0 >> 6) * 128 + (tl0 & 63);
                    const size_t c1 = vb + (tl1 >> 6) * 128 + (tl1 & 63);
                    const float e0 = dd ? v01 : v00;
                    const float e1 = dd ? v11 : v10;
                    const __nv_bfloat16 e0h = __float2bfloat16(e0);
                    const __nv_bfloat16 e1h = __float2bfloat16(e1);
                    vpack[c0]      = e0h;
                    vpack[c0 + 64] = __float2bfloat16(e0 - __bfloat162float(e0h));
                    vpack[c1]      = e1h;
                    vpack[c1 + 64] = __float2bfloat16(e1 - __bfloat162float(e1h));
                }
            }
        }
    }
}

// ---------------------------------------------------------------------------
// Tensor-core causal flash attention (unchanged from R7 — verified)
// ---------------------------------------------------------------------------
#define ASTR  136
#define ASTRB 272
#define TILEB (64 * ASTRB)                 // 17408
#define ATTN_SMEM (4 * TILEB)              // 69632 bytes

__global__ __launch_bounds__(128) void attn_mma(
    const __nv_bfloat16* __restrict__ qpack,
    const __nv_bfloat16* __restrict__ kpack,
    const __nv_bfloat16* __restrict__ vpack,
    __nv_bfloat16* __restrict__ outp)
{
    extern __shared__ __align__(16) unsigned char smraw[];

    const int qt   = (gridDim.x - 1) - blockIdx.x;
    const int h    = blockIdx.y;
    const int b    = blockIdx.z;
    const int tid  = threadIdx.x;
    const int wid  = tid >> 5;
    const int lane = tid & 31;
    const int q0   = qt * 64;
    const int bh   = b * NH + h;

    const uint32_t KsB = smem_u32(smraw);
    const uint32_t QsB = KsB + TILEB;            // Q staged in K-buf1
    const uint32_t VsB = KsB + 2 * TILEB;

    const __nv_bfloat16* qrows = qpack + ((size_t)bh * TSEQ + q0) * 128;
    const __nv_bfloat16* krows = kpack + (size_t)bh * TSEQ * 128;
    const __nv_bfloat16* vrows = vpack + (size_t)bh * HD * (2 * TSEQ);

    auto load_kv = [&](int kt, int buf) {
        const uint32_t kdst = KsB + buf * TILEB;
        const uint32_t vdst = VsB + buf * TILEB;
        #pragma unroll
        for (int i = 0; i < 8; i++) {
            const int idx = i * 128 + tid;
            const int r = idx >> 4;
            const int c = idx & 15;
            CP_ASYNC16(kdst + (uint32_t)(r * ASTRB + c * 16),
                       krows + ((size_t)(kt * 64 + r)) * 128 + c * 8);
            CP_ASYNC16(vdst + (uint32_t)(r * ASTRB + c * 16),
                       vrows + (size_t)r * (2 * TSEQ) + kt * 128 + c * 8);
        }
    };

    #pragma unroll
    for (int i = 0; i < 8; i++) {
        const int idx = i * 128 + tid;
        const int r = idx >> 4;
        const int c = idx & 15;
        CP_ASYNC16(QsB + (uint32_t)(r * ASTRB + c * 16),
                   qrows + (size_t)r * 128 + c * 8);
    }
    load_kv(0, 0);
    CP_COMMIT();
    CP_WAIT(0);
    __syncthreads();

    const int lrow  = lane & 15;
    const int lcolb = (lane >> 4) << 4;
    uint32_t ahi[4][4], alo[4][4];
    #pragma unroll
    for (int ks = 0; ks < 4; ks++) {
        const uint32_t ad = QsB + (uint32_t)((16 * wid + lrow) * ASTRB + ks * 32) + lcolb;
        LDSM_X4(ahi[ks][0], ahi[ks][1], ahi[ks][2], ahi[ks][3], ad);
        LDSM_X4(alo[ks][0], alo[ks][1], alo[ks][2], alo[ks][3], ad + 128);
    }
    __syncthreads();

    float oacc[8][4];
    #pragma unroll
    for (int t = 0; t < 8; t++)
        #pragma unroll
        for (int j = 0; j < 4; j++) oacc[t][j] = 0.f;
    float m0r = -1.0e30f, m1r = -1.0e30f, l0 = 0.f, l1 = 0.f;

    const int rl0 = 16 * wid + (lane >> 2);
    const int rl1 = rl0 + 8;

    for (int kt = 0; kt <= qt; kt++) {
        if (kt < qt) { load_kv(kt + 1, (kt + 1) & 1); CP_COMMIT(); }

        const uint32_t kB = KsB + (kt & 1) * TILEB;
        const uint32_t vB = VsB + (kt & 1) * TILEB;

        float sf[8][4];
        #pragma unroll
        for (int t = 0; t < 8; t++)
            #pragma unroll
            for (int j = 0; j < 4; j++) sf[t][j] = 0.f;

        #pragma unroll
        for (int ks = 0; ks < 4; ks++) {
            uint32_t bhi[4][4], blo[4][4];
            #pragma unroll
            for (int g = 0; g < 4; g++) {
                const uint32_t bd = kB +
                    (uint32_t)((g * 16 + lrow) * ASTRB + ks * 32) + lcolb;
                LDSM_X4(bhi[g][0], bhi[g][1], bhi[g][2], bhi[g][3], bd);
                LDSM_X4(blo[g][0], blo[g][1], blo[g][2], blo[g][3], bd + 128);
            }
            #pragma unroll
            for (int g = 0; g < 4; g++)
                #pragma unroll
                for (int hh = 0; hh < 2; hh++) {
                    const int t = 2 * g + hh;
                    MMA_BF16(sf[t][0], sf[t][1], sf[t][2], sf[t][3],
                             ahi[ks][0], ahi[ks][1], ahi[ks][2], ahi[ks][3],
                             bhi[g][hh], bhi[g][2 + hh]);
                    MMA_BF16(sf[t][0], sf[t][1], sf[t][2], sf[t][3],
                             ahi[ks][0], ahi[ks][1], ahi[ks][2], ahi[ks][3],
                             blo[g][hh], blo[g][2 + hh]);
                    MMA_BF16(sf[t][0], sf[t][1], sf[t][2], sf[t][3],
                             alo[ks][0], alo[ks][1], alo[ks][2], alo[ks][3],
                             bhi[g][hh], bhi[g][2 + hh]);
                }
        }

        if (kt == qt) {
            #pragma unroll
            for (int t = 0; t < 8; t++) {
                const int c = t * 8 + 2 * (lane & 3);
                if (c     > rl0) sf[t][0] = -1.0e30f;
                if (c + 1 > rl0) sf[t][1] = -1.0e30f;
                if (c     > rl1) sf[t][2] = -1.0e30f;
                if (c + 1 > rl1) sf[t][3] = -1.0e30f;
            }
        }

        float rm0 = -1.0e30f, rm1 = -1.0e30f;
        #pragma unroll
        for (int t = 0; t < 8; t++) {
            rm0 = fmaxf(rm0, fmaxf(sf[t][0], sf[t][1]));
            rm1 = fmaxf(rm1, fmaxf(sf[t][2], sf[t][3]));
        }
        rm0 = fmaxf(rm0, __shfl_xor_sync(0xffffffffu, rm0, 1));
        rm0 = fmaxf(rm0, __shfl_xor_sync(0xffffffffu, rm0, 2));
        rm1 = fmaxf(rm1, __shfl_xor_sync(0xffffffffu, rm1, 1));
        rm1 = fmaxf(rm1, __shfl_xor_sync(0xffffffffu, rm1, 2));
        const float mn0 = fmaxf(m0r, rm0);
        const float mn1 = fmaxf(m1r, rm1);

        float sum0 = 0.f, sum1 = 0.f;
        #pragma unroll
        for (int t = 0; t < 8; t++) {
            sf[t][0] = __expf(sf[t][0] - mn0);
            sf[t][1] = __expf(sf[t][1] - mn0);
            sf[t][2] = __expf(sf[t][2] - mn1);
            sf[t][3] = __expf(sf[t][3] - mn1);
            sum0 += sf[t][0] + sf[t][1];
            sum1 += sf[t][2] + sf[t][3];
        }
        sum0 += __shfl_xor_sync(0xffffffffu, sum0, 1);
        sum0 += __shfl_xor_sync(0xffffffffu, sum0, 2);
        sum1 += __shfl_xor_sync(0xffffffffu, sum1, 1);
        sum1 += __shfl_xor_sync(0xffffffffu, sum1, 2);

        const float al0 = __expf(m0r - mn0);
        const float al1 = __expf(m1r - mn1);
        l0 = l0 * al0 + sum0;  m0r = mn0;
        l1 = l1 * al1 + sum1;  m1r = mn1;
        #pragma unroll
        for (int t = 0; t < 8; t++) {
            oacc[t][0] *= al0; oacc[t][1] *= al0;
            oacc[t][2] *= al1; oacc[t][3] *= al1;
        }

        uint32_t phi[4][4], plo[4][4];
        #pragma unroll
        for (int ks = 0; ks < 4; ks++) {
            const float* e0 = sf[2 * ks];
            const float* e1 = sf[2 * ks + 1];
            #pragma unroll
            for (int q = 0; q < 2; q++) {
                const float* e = q ? e1 : e0;
                float hx0 = __bfloat162float(__float2bfloat16(e[0]));
                float hx1 = __bfloat162float(__float2bfloat16(e[1]));
                float hx2 = __bfloat162float(__float2bfloat16(e[2]));
                float hx3 = __bfloat162float(__float2bfloat16(e[3]));
                phi[ks][2 * q]     = pack_bf16(e[0], e[1]);
                phi[ks][2 * q + 1] = pack_bf16(e[2], e[3]);
                plo[ks][2 * q]     = pack_bf16(e[0] - hx0, e[1] - hx1);
                plo[ks][2 * q + 1] = pack_bf16(e[2] - hx2, e[3] - hx3);
            }
        }

        #pragma unroll
        for (int ks = 0; ks < 4; ks++) {
            uint32_t bhi[4][4], blo[4][4];
            #pragma unroll
            for (int g = 0; g < 4; g++) {
                const uint32_t bd = vB +
                    (uint32_t)((g * 16 + lrow) * ASTRB + ks * 32) + lcolb;
                LDSM_X4(bhi[g][0], bhi[g][1], bhi[g][2], bhi[g][3], bd);
                LDSM_X4(blo[g][0], blo[g][1], blo[g][2], blo[g][3], bd + 128);
            }
            #pragma unroll
            for (int g = 0; g < 4; g++)
                #pragma unroll
                for (int hh = 0; hh < 2; hh++) {
                    const int t = 2 * g + hh;
                    MMA_BF16(oacc[t][0], oacc[t][1], oacc[t][2], oacc[t][3],
                             phi[ks][0], phi[ks][1], phi[ks][2], phi[ks][3],
                             bhi[g][hh], bhi[g][2 + hh]);
                    MMA_BF16(oacc[t][0], oacc[t][1], oacc[t][2], oacc[t][3],
                             phi[ks][0], phi[ks][1], phi[ks][2], phi[ks][3],
                             blo[g][hh], blo[g][2 + hh]);
                    MMA_BF16(oacc[t][0], oacc[t][1], oacc[t][2], oacc[t][3],
                             plo[ks][0], plo[ks][1], plo[ks][2], plo[ks][3],
                             bhi[g][hh], bhi[g][2 + hh]);
                }
        }

        if (kt < qt) {
            CP_WAIT(0);
            __syncthreads();
        }
    }

    const float inv0 = 1.0f / l0;
    const float inv1 = 1.0f / l1;
    const int r0g = q0 + rl0;
    const int r1g = q0 + rl1;
    const size_t pb0 = ((size_t)b * TSEQ + r0g) * K2 + h * HD;
    const size_t pb1 = ((size_t)b * TSEQ + r1g) * K2 + h * HD;
    #pragma unroll
    for (int t = 0; t < 8; t++) {
        const int cg = t * 8 + 2 * (lane & 3);
        const float v00 = oacc[t][0] * inv0, v01 = oacc[t][1] * inv0;
        const float v10 = oacc[t][2] * inv1, v11 = oacc[t][3] * inv1;
        const uint32_t h0 = pack_bf16(v00, v01);
        const uint32_t h1 = pack_bf16(v10, v11);
        __nv_bfloat162 h0b = *reinterpret_cast<const __nv_bfloat162*>(&h0);
        __nv_bfloat162 h1b = *reinterpret_cast<const __nv_bfloat162*>(&h1);
        const uint32_t l0p = pack_bf16(v00 - __bfloat162float(h0b.x),
                                       v01 - __bfloat162float(h0b.y));
        const uint32_t l1p = pack_bf16(v10 - __bfloat162float(h1b.x),
                                       v11 - __bfloat162float(h1b.y));
        *reinterpret_cast<uint32_t*>(&outp[pb0 + cg])        = h0;
        *reinterpret_cast<uint32_t*>(&outp[pb0 + CDIM + cg]) = l0p;
        *reinterpret_cast<uint32_t*>(&outp[pb1 + cg])        = h1;
        *reinterpret_cast<uint32_t*>(&outp[pb1 + CDIM + cg]) = l1p;
    }
}

// ---------------------------------------------------------------------------
// Launch
// ---------------------------------------------------------------------------
extern "C" void kernel_launch(void* const* d_in, const int* in_sizes, int n_in,
                              void* d_out, int out_size)
{
    const float* x     = (const float*)d_in[0];
    const float* Wqkv  = (const float*)d_in[1];
    const float* bqkv  = (const float*)d_in[2];
    const float* Wproj = (const float*)d_in[3];
    const float* bproj = (const float*)d_in[4];
    float* out = (float*)d_out;

    __nv_bfloat16 *ahat, *bqkvp, *bprojp, *qp, *kp, *vp;
    cudaGetSymbolAddress((void**)&ahat,   g_ahat);
    cudaGetSymbolAddress((void**)&bqkvp,  g_bqkv);
    cudaGetSymbolAddress((void**)&bprojp, g_bproj);
    cudaGetSymbolAddress((void**)&qp,     g_qpack);
    cudaGetSymbolAddress((void**)&kp,     g_kpack);
    cudaGetSymbolAddress((void**)&vp,     g_vpack);

    cudaFuncSetAttribute(attn_mma,
                         cudaFuncAttributeMaxDynamicSharedMemorySize, ATTN_SMEM);
    cudaFuncSetAttribute(gemm_mma,
                         cudaFuncAttributeMaxDynamicSharedMemorySize, GEMM_SMEM);
    cudaFuncSetAttribute(gemm_qkv,
                         cudaFuncAttributeMaxDynamicSharedMemorySize, GEMM_SMEM);

    // Pack weights -> [N, 2K] = [hi|lo]
    {
        dim3 bb(32, 8);
        convert_split_wT<<<dim3(THREEC / 32, CDIM / 32), bb>>>(Wqkv, bqkvp, CDIM, THREEC);
        convert_split_wT<<<dim3(CDIM / 32, CDIM / 32), bb>>>(Wproj, bprojp, CDIM, CDIM);
    }

    // 1) Pack x; QKV GEMM writes packed Q/K/V directly
    convert_split_act<<<(MROWS * CDIM + 255) / 256, 256>>>(x, ahat, MROWS * CDIM, CDIM);
    gemm_qkv<<<dim3(THREEC / 128, MROWS / 128), GEMM_THREADS, GEMM_SMEM>>>(
        ahat, bqkvp, bqkv, qp, kp, vp);

    // 2) Pipelined attention -> packed proj input
    attn_mma<<<dim3(TSEQ / 64, NH, BATCH), 128, ATTN_SMEM>>>(qp, kp, vp, ahat);

    // 3) Output projection
    gemm_mma<<<dim3(CDIM / 128, MROWS / 128), GEMM_THREADS, GEMM_SMEM>>>(
        ahat, bprojp, bproj, out, MROWS, CDIM);
}

// round 12
// speedup vs baseline: 1.0369x; 1.0369x over previous
#include <cuda_runtime.h>
#include <cuda_bf16.h>
#include <math.h>
#include <cstdint>

// Problem constants
#define BATCH 2
#define TSEQ  2048
#define CDIM  1024
#define NH    16
#define HD    64
#define THREEC (3*CDIM)
#define MROWS (BATCH*TSEQ)   // 4096
#define K2    (2*CDIM)       // [hi|lo] packed K = 2048

// ---------------------------------------------------------------------------
// Scratch (__device__ globals; allocation-free rule)
// ---------------------------------------------------------------------------
__device__ __nv_bfloat16 g_ahat[(size_t)MROWS * K2];       // packed activations
__device__ __nv_bfloat16 g_bqkv[(size_t)THREEC * K2];      // packed Wqkv^T
__device__ __nv_bfloat16 g_bproj[(size_t)CDIM * K2];       // packed Wproj^T
// Pre-split attention operands (written directly by the QKV GEMM epilogue)
__device__ __nv_bfloat16 g_qpack[(size_t)BATCH * NH * TSEQ * 128];
__device__ __nv_bfloat16 g_kpack[(size_t)BATCH * NH * TSEQ * 128];
__device__ __nv_bfloat16 g_vpack[(size_t)BATCH * NH * HD * 2 * TSEQ];

// ---------------------------------------------------------------------------
// Helpers (base-ISA only: cp.async / ldmatrix / mma.sync)
// ---------------------------------------------------------------------------
__device__ __forceinline__ uint32_t smem_u32(const void* p) {
    uint32_t a;
    asm("{ .reg .u64 t; cvta.to.shared.u64 t, %1; cvt.u32.u64 %0, t; }"
        : "=r"(a) : "l"(p));
    return a;
}
#define CP_ASYNC16(smaddr, gptr) \
    asm volatile("cp.async.cg.shared.global [%0], [%1], 16;" \
                 :: "r"(smaddr), "l"(gptr))
#define CP_COMMIT() asm volatile("cp.async.commit_group;" ::: "memory")
#define CP_WAIT(n)  asm volatile("cp.async.wait_group %0;" :: "n"(n) : "memory")

#define LDSM_X4(r0, r1, r2, r3, addr) \
    asm volatile("ldmatrix.sync.aligned.m8n8.x4.shared.b16 {%0,%1,%2,%3}, [%4];" \
                 : "=r"(r0), "=r"(r1), "=r"(r2), "=r"(r3) : "r"(addr))

#define MMA_BF16(c0, c1, c2, c3, a0, a1, a2, a3, b0, b1) \
    asm volatile("mma.sync.aligned.m16n8k16.row.col.f32.bf16.bf16.f32 " \
                 "{%0,%1,%2,%3}, {%4,%5,%6,%7}, {%8,%9}, {%0,%1,%2,%3};" \
                 : "+f"(c0), "+f"(c1), "+f"(c2), "+f"(c3) \
                 : "r"(a0), "r"(a1), "r"(a2), "r"(a3), "r"(b0), "r"(b1))

__device__ __forceinline__ uint32_t pack_bf16(float x, float y) {
    __nv_bfloat162 h = __floats2bfloat162_rn(x, y);
    return *reinterpret_cast<uint32_t*>(&h);
}

// ---------------------------------------------------------------------------
// Split-convert activations: A[M,K] fp32 -> Ahat[M,2K] bf16 = [hi | lo]
// ---------------------------------------------------------------------------
__global__ void convert_split_act(const float* __restrict__ in,
                                  __nv_bfloat16* __restrict__ out, int MK, int K)
{
    int idx = blockIdx.x * blockDim.x + threadIdx.x;
    if (idx >= MK) return;
    int m = idx / K, k = idx - m * K;
    float v = in[idx];
    __nv_bfloat16 hi = __float2bfloat16(v);
    __nv_bfloat16 lo = __float2bfloat16(v - __bfloat162float(hi));
    size_t base = (size_t)m * (2 * K);
    out[base + k]     = hi;
    out[base + K + k] = lo;
}

// ---------------------------------------------------------------------------
// Transpose + split-convert weights: W[K,N] fp32 -> Bhat[N,2K] bf16 = [hi|lo]
// ---------------------------------------------------------------------------
__global__ void convert_split_wT(const float* __restrict__ W,
                                 __nv_bfloat16* __restrict__ out, int K, int N)
{
    __shared__ float t[32][33];
    const int tx = threadIdx.x, ty = threadIdx.y;   // block (32, 8)
    const int n0 = blockIdx.x * 32, k0 = blockIdx.y * 32;
    #pragma unroll
    for (int j = 0; j < 4; j++)
        t[ty + j * 8][tx] = W[(size_t)(k0 + ty + j * 8) * N + n0 + tx];
    __syncthreads();
    #pragma unroll
    for (int j = 0; j < 4; j++) {
        const int nn = ty + j * 8;
        float v = t[tx][nn];
        __nv_bfloat16 hi = __float2bfloat16(v);
        __nv_bfloat16 lo = __float2bfloat16(v - __bfloat162float(hi));
        size_t base = (size_t)(n0 + nn) * (2 * K) + k0 + tx;
        out[base]     = hi;
        out[base + K] = lo;
    }
}

// ---------------------------------------------------------------------------
// Shared GEMM mainloop config: 128x128 CTA tile, 8 warps (256 thr),
// 32x64 warp tile. [hi|lo] + register 3-term split.
// MMA issue order: term-outer, so consecutive volatile HMMAs target
// independent accumulators (per-acc term order unchanged -> bit-identical).
// ---------------------------------------------------------------------------
#define GBK   32
#define NSTG  (CDIM / GBK)            // 32
#define ROWB  144
#define STAGE_BYTES (128 * ROWB)      // 18432
#define STAGES 2
#define GEMM_SMEM (2 * STAGES * STAGE_BYTES)   // 73728 bytes
#define GEMM_THREADS 256

#define GEMM_MAINLOOP(Aptr, Bptr)                                              \
    extern __shared__ __align__(16) unsigned char gsm[];                       \
    const int tid  = threadIdx.x;                                              \
    const int wid  = tid >> 5;                                                 \
    const int lane = tid & 31;                                                 \
    const int wm   = wid & 3;                                                  \
    const int wn   = wid >> 2;                                                 \
    const int row0 = blockIdx.y * 128;                                         \
    const int col0 = blockIdx.x * 128;                                         \
    const uint32_t smA_b = smem_u32(gsm);                                      \
    const uint32_t smB_b = smA_b + STAGES * STAGE_BYTES;                       \
    const __nv_bfloat16* Arow = (Aptr) + (size_t)row0 * K2;                    \
    const __nv_bfloat16* Brow = (Bptr) + (size_t)col0 * K2;                    \
    auto load_stage = [&](int s, int buf) {                                    \
        const int k0 = s * GBK;                                                \
        const uint32_t ao = smA_b + buf * STAGE_BYTES;                         \
        const uint32_t bo = smB_b + buf * STAGE_BYTES;                         \
        _Pragma("unroll")                                                      \
        for (int i = 0; i < 4; i++) {                                          \
            const int idx = i * 256 + tid;                                     \
            const int r   = idx >> 3;                                          \
            const int c   = idx & 7;                                           \
            const int cc  = c & 3;                                             \
            const int gofs = (c < 4) ? (k0 + cc * 8) : (CDIM + k0 + cc * 8);   \
            const uint32_t so = (uint32_t)(r * ROWB + cc * 16 + ((c < 4) ? 0 : 64)); \
            CP_ASYNC16(ao + so, Arow + (size_t)r * K2 + gofs);                 \
            CP_ASYNC16(bo + so, Brow + (size_t)r * K2 + gofs);                 \
        }                                                                      \
    };                                                                         \
    float acc[2][8][4];                                                        \
    _Pragma("unroll")                                                          \
    for (int i = 0; i < 2; i++)                                                \
        _Pragma("unroll")                                                      \
        for (int j = 0; j < 8; j++)                                            \
            _Pragma("unroll")                                                  \
            for (int k = 0; k < 4; k++) acc[i][j][k] = 0.f;                    \
    const int lrow = lane & 15;                                                \
    const int lcol = (lane >> 4) << 4;                                         \
    load_stage(0, 0);                                                          \
    CP_COMMIT();                                                               \
    for (int s = 0; s < NSTG; s++) {                                           \
        CP_WAIT(0);                                                            \
        __syncthreads();                                                       \
        if (s + 1 < NSTG) { load_stage(s + 1, (s + 1) & 1); CP_COMMIT(); }     \
        const int buf = s & 1;                                                 \
        const uint32_t aB = smA_b + buf * STAGE_BYTES;                         \
        const uint32_t bB = smB_b + buf * STAGE_BYTES;                         \
        _Pragma("unroll")                                                      \
        for (int ks = 0; ks < 2; ks++) {                                       \
            uint32_t ahi[2][4], alo[2][4], bhi[4][4], blo[4][4];               \
            _Pragma("unroll")                                                  \
            for (int fm = 0; fm < 2; fm++) {                                   \
                const uint32_t ad = aB +                                       \
                    (uint32_t)((wm * 32 + fm * 16 + lrow) * ROWB + ks * 32) + lcol; \
                LDSM_X4(ahi[fm][0], ahi[fm][1], ahi[fm][2], ahi[fm][3], ad);   \
                LDSM_X4(alo[fm][0], alo[fm][1], alo[fm][2], alo[fm][3], ad + 64); \
            }                                                                  \
            _Pragma("unroll")                                                  \
            for (int g = 0; g < 4; g++) {                                      \
                const uint32_t bd = bB +                                       \
                    (uint32_t)((wn * 64 + g * 16 + lrow) * ROWB + ks * 32) + lcol; \
                LDSM_X4(bhi[g][0], bhi[g][1], bhi[g][2], bhi[g][3], bd);       \
                LDSM_X4(blo[g][0], blo[g][1], blo[g][2], blo[g][3], bd + 64);  \
            }                                                                  \
            /* term-outer: consecutive MMAs hit independent accumulators */    \
            _Pragma("unroll")                                                  \
            for (int term = 0; term < 3; term++)                               \
                _Pragma("unroll")                                              \
                for (int fm = 0; fm < 2; fm++)                                 \
                    _Pragma("unroll")                                          \
                    for (int fn = 0; fn < 8; fn++) {                           \
                        const int g = fn >> 1, h = fn & 1;                     \
                        const uint32_t* af = (term == 2) ? alo[fm] : ahi[fm];  \
                        const uint32_t* bf = (term == 1) ? blo[g]  : bhi[g];   \
                        MMA_BF16(acc[fm][fn][0], acc[fm][fn][1],               \
                                 acc[fm][fn][2], acc[fm][fn][3],               \
                                 af[0], af[1], af[2], af[3],                   \
                                 bf[h], bf[2 + h]);                            \
                    }                                                          \
        }                                                                      \
    }

// ---------------------------------------------------------------------------
// Proj GEMM: plain fp32 output + bias
// ---------------------------------------------------------------------------
__global__ __launch_bounds__(GEMM_THREADS) void gemm_mma(
    const __nv_bfloat16* __restrict__ A,
    const __nv_bfloat16* __restrict__ B,
    const float* __restrict__ bias,
    float* __restrict__ C, int M, int N)
{
    GEMM_MAINLOOP(A, B)

    const int erow = lane >> 2;
    const int ecol = (lane & 3) << 1;
    #pragma unroll
    for (int fm = 0; fm < 2; fm++) {
        const int r0g = row0 + wm * 32 + fm * 16 + erow;
        #pragma unroll
        for (int fn = 0; fn < 8; fn++) {
            const int cg = col0 + wn * 64 + fn * 8 + ecol;
            const float b0 = bias[cg], b1 = bias[cg + 1];
            float2 v0 = make_float2(acc[fm][fn][0] + b0, acc[fm][fn][1] + b1);
            float2 v1 = make_float2(acc[fm][fn][2] + b0, acc[fm][fn][3] + b1);
            *reinterpret_cast<float2*>(&C[(size_t)r0g * N + cg]) = v0;
            *reinterpret_cast<float2*>(&C[(size_t)(r0g + 8) * N + cg]) = v1;
        }
    }
}

// ---------------------------------------------------------------------------
// QKV GEMM with fused pack epilogue (writes qpack/kpack/vpack directly)
// ---------------------------------------------------------------------------
__global__ __launch_bounds__(GEMM_THREADS) void gemm_qkv(
    const __nv_bfloat16* __restrict__ A,
    const __nv_bfloat16* __restrict__ B,
    const float* __restrict__ bias,
    __nv_bfloat16* __restrict__ qpack,
    __nv_bfloat16* __restrict__ kpack,
    __nv_bfloat16* __restrict__ vpack)
{
    GEMM_MAINLOOP(A, B)

    const int erow = lane >> 2;
    const int ecol = (lane & 3) << 1;
    const int sec  = col0 >> 10;                      // 0=Q 1=K 2=V
    const int hh   = ((col0 & 1023) >> 6) + wn;       // head (per-warp constant)
    const float scale = (sec == 0) ? 0.125f : 1.0f;

    #pragma unroll
    for (int fm = 0; fm < 2; fm++) {
        const int t0g = row0 + wm * 32 + fm * 16 + erow;
        const int bidx = t0g >> 11;
        const int bh   = bidx * NH + hh;
        const int tl0  = t0g & 2047;
        const int tl1  = tl0 + 8;
        #pragma unroll
        for (int fn = 0; fn < 8; fn++) {
            const int cg = col0 + wn * 64 + fn * 8 + ecol;
            const int d  = (cg & 63);
            const float b0 = bias[cg], b1 = bias[cg + 1];
            const float v00 = (acc[fm][fn][0] + b0) * scale;
            const float v01 = (acc[fm][fn][1] + b1) * scale;
            const float v10 = (acc[fm][fn][2] + b0) * scale;
            const float v11 = (acc[fm][fn][3] + b1) * scale;

            const uint32_t h0 = pack_bf16(v00, v01);
            const uint32_t h1 = pack_bf16(v10, v11);
            const __nv_bfloat162 h0b = *reinterpret_cast<const __nv_bfloat162*>(&h0);
            const __nv_bfloat162 h1b = *reinterpret_cast<const __nv_bfloat162*>(&h1);
            const uint32_t l0 = pack_bf16(v00 - __bfloat162float(h0b.x),
                                          v01 - __bfloat162float(h0b.y));
            const uint32_t l1 = pack_bf16(v10 - __bfloat162float(h1b.x),
                                          v11 - __bfloat162float(h1b.y));

            if (sec < 2) {
                __nv_bfloat16* dst = (sec == 0) ? qpack : kpack;
                const size_t r0 = ((size_t)bh * TSEQ + tl0) * 128 + d;
                const size_t r1 = ((size_t)bh * TSEQ + tl1) * 128 + d;
                *reinterpret_cast<uint32_t*>(&dst[r0])      = h0;
                *reinterpret_cast<uint32_t*>(&dst[r0 + 64]) = l0;
                *reinterpret_cast<uint32_t*>(&dst[r1])      = h1;
                *reinterpret_cast<uint32_t*>(&dst[r1 + 64]) = l1;
            } else {
                #pragma unroll
                for (int dd = 0; dd < 2; dd++) {
                    const size_t vb = ((size_t)bh * HD + d + dd) * (2 * TSEQ);
                    const size_t c0 = vb + (tl0 >> 6) * 128 + (tl0 & 63);
                    const size_t c1 = vb + (tl1 >> 6) * 128 + (tl1 & 63);
                    const float e0 = dd ? v01 : v00;
                    const float e1 = dd ? v11 : v10;
                    const __nv_bfloat16 e0h = __float2bfloat16(e0);
                    const __nv_bfloat16 e1h = __float2bfloat16(e1);
                    vpack[c0]      = e0h;
                    vpack[c0 + 64] = __float2bfloat16(e0 - __bfloat162float(e0h));
                    vpack[c1]      = e1h;
                    vpack[c1 + 64] = __float2bfloat16(e1 - __bfloat162float(e1h));
                }
            }
        }
    }
}

// ---------------------------------------------------------------------------
// Tensor-core causal flash attention, full 3-term split on S and PV
// (R8 numerics), MMA issue order term-outer for independent accumulators.
// ---------------------------------------------------------------------------
#define ASTR  136
#define ASTRB 272
#define TILEB (64 * ASTRB)                 // 17408
#define ATTN_SMEM (4 * TILEB)              // 69632 bytes

__global__ __launch_bounds__(128) void attn_mma(
    const __nv_bfloat16* __restrict__ qpack,
    const __nv_bfloat16* __restrict__ kpack,
    const __nv_bfloat16* __restrict__ vpack,
    __nv_bfloat16* __restrict__ outp)
{
    extern __shared__ __align__(16) unsigned char smraw[];

    const int qt   = (gridDim.x - 1) - blockIdx.x;
    const int h    = blockIdx.y;
    const int b    = blockIdx.z;
    const int tid  = threadIdx.x;
    const int wid  = tid >> 5;
    const int lane = tid & 31;
    const int q0   = qt * 64;
    const int bh   = b * NH + h;

    const uint32_t KsB = smem_u32(smraw);
    const uint32_t QsB = KsB + TILEB;            // Q staged in K-buf1
    const uint32_t VsB = KsB + 2 * TILEB;

    const __nv_bfloat16* qrows = qpack + ((size_t)bh * TSEQ + q0) * 128;
    const __nv_bfloat16* krows = kpack + (size_t)bh * TSEQ * 128;
    const __nv_bfloat16* vrows = vpack + (size_t)bh * HD * (2 * TSEQ);

    auto load_kv = [&](int kt, int buf) {
        const uint32_t kdst = KsB + buf * TILEB;
        const uint32_t vdst = VsB + buf * TILEB;
        #pragma unroll
        for (int i = 0; i < 8; i++) {
            const int idx = i * 128 + tid;
            const int r = idx >> 4;
            const int c = idx & 15;
            CP_ASYNC16(kdst + (uint32_t)(r * ASTRB + c * 16),
                       krows + ((size_t)(kt * 64 + r)) * 128 + c * 8);
            CP_ASYNC16(vdst + (uint32_t)(r * ASTRB + c * 16),
                       vrows + (size_t)r * (2 * TSEQ) + kt * 128 + c * 8);
        }
    };

    #pragma unroll
    for (int i = 0; i < 8; i++) {
        const int idx = i * 128 + tid;
        const int r = idx >> 4;
        const int c = idx & 15;
        CP_ASYNC16(QsB + (uint32_t)(r * ASTRB + c * 16),
                   qrows + (size_t)r * 128 + c * 8);
    }
    load_kv(0, 0);
    CP_COMMIT();
    CP_WAIT(0);
    __syncthreads();

    const int lrow  = lane & 15;
    const int lcolb = (lane >> 4) << 4;
    uint32_t ahi[4][4], alo[4][4];
    #pragma unroll
    for (int ks = 0; ks < 4; ks++) {
        const uint32_t ad = QsB + (uint32_t)((16 * wid + lrow) * ASTRB + ks * 32) + lcolb;
        LDSM_X4(ahi[ks][0], ahi[ks][1], ahi[ks][2], ahi[ks][3], ad);
        LDSM_X4(alo[ks][0], alo[ks][1], alo[ks][2], alo[ks][3], ad + 128);
    }
    __syncthreads();

    float oacc[8][4];
    #pragma unroll
    for (int t = 0; t < 8; t++)
        #pragma unroll
        for (int j = 0; j < 4; j++) oacc[t][j] = 0.f;
    float m0r = -1.0e30f, m1r = -1.0e30f, l0 = 0.f, l1 = 0.f;

    const int rl0 = 16 * wid + (lane >> 2);
    const int rl1 = rl0 + 8;

    for (int kt = 0; kt <= qt; kt++) {
        if (kt < qt) { load_kv(kt + 1, (kt + 1) & 1); CP_COMMIT(); }

        const uint32_t kB = KsB + (kt & 1) * TILEB;
        const uint32_t vB = VsB + (kt & 1) * TILEB;

        float sf[8][4];
        #pragma unroll
        for (int t = 0; t < 8; t++)
            #pragma unroll
            for (int j = 0; j < 4; j++) sf[t][j] = 0.f;

        #pragma unroll
        for (int ks = 0; ks < 4; ks++) {
            uint32_t bhi[4][4], blo[4][4];
            #pragma unroll
            for (int g = 0; g < 4; g++) {
                const uint32_t bd = kB +
                    (uint32_t)((g * 16 + lrow) * ASTRB + ks * 32) + lcolb;
                LDSM_X4(bhi[g][0], bhi[g][1], bhi[g][2], bhi[g][3], bd);
                LDSM_X4(blo[g][0], blo[g][1], blo[g][2], blo[g][3], bd + 128);
            }
            // term-outer: 8 independent accumulators between reuses
            #pragma unroll
            for (int term = 0; term < 3; term++)
                #pragma unroll
                for (int g = 0; g < 4; g++)
                    #pragma unroll
                    for (int hh = 0; hh < 2; hh++) {
                        const int t = 2 * g + hh;
                        const uint32_t* af = (term == 2) ? alo[ks] : ahi[ks];
                        const uint32_t* bf = (term == 1) ? blo[g]  : bhi[g];
                        MMA_BF16(sf[t][0], sf[t][1], sf[t][2], sf[t][3],
                                 af[0], af[1], af[2], af[3],
                                 bf[hh], bf[2 + hh]);
                    }
        }

        if (kt == qt) {
            #pragma unroll
            for (int t = 0; t < 8; t++) {
                const int c = t * 8 + 2 * (lane & 3);
                if (c     > rl0) sf[t][0] = -1.0e30f;
                if (c + 1 > rl0) sf[t][1] = -1.0e30f;
                if (c     > rl1) sf[t][2] = -1.0e30f;
                if (c + 1 > rl1) sf[t][3] = -1.0e30f;
            }
        }

        float rm0 = -1.0e30f, rm1 = -1.0e30f;
        #pragma unroll
        for (int t = 0; t < 8; t++) {
            rm0 = fmaxf(rm0, fmaxf(sf[t][0], sf[t][1]));
            rm1 = fmaxf(rm1, fmaxf(sf[t][2], sf[t][3]));
        }
        rm0 = fmaxf(rm0, __shfl_xor_sync(0xffffffffu, rm0, 1));
        rm0 = fmaxf(rm0, __shfl_xor_sync(0xffffffffu, rm0, 2));
        rm1 = fmaxf(rm1, __shfl_xor_sync(0xffffffffu, rm1, 1));
        rm1 = fmaxf(rm1, __shfl_xor_sync(0xffffffffu, rm1, 2));
        const float mn0 = fmaxf(m0r, rm0);
        const float mn1 = fmaxf(m1r, rm1);

        float sum0 = 0.f, sum1 = 0.f;
        #pragma unroll
        for (int t = 0; t < 8; t++) {
            sf[t][0] = __expf(sf[t][0] - mn0);
            sf[t][1] = __expf(sf[t][1] - mn0);
            sf[t][2] = __expf(sf[t][2] - mn1);
            sf[t][3] = __expf(sf[t][3] - mn1);
            sum0 += sf[t][0] + sf[t][1];
            sum1 += sf[t][2] + sf[t][3];
        }
        sum0 += __shfl_xor_sync(0xffffffffu, sum0, 1);
        sum0 += __shfl_xor_sync(0xffffffffu, sum0, 2);
        sum1 += __shfl_xor_sync(0xffffffffu, sum1, 1);
        sum1 += __shfl_xor_sync(0xffffffffu, sum1, 2);

        const float al0 = __expf(m0r - mn0);
        const float al1 = __expf(m1r - mn1);
        l0 = l0 * al0 + sum0;  m0r = mn0;
        l1 = l1 * al1 + sum1;  m1r = mn1;
        #pragma unroll
        for (int t = 0; t < 8; t++) {
            oacc[t][0] *= al0; oacc[t][1] *= al0;
            oacc[t][2] *= al1; oacc[t][3] *= al1;
        }

        // ---- P fragments: full hi/lo split (verified numerics) ----
        uint32_t phi[4][4], plo[4][4];
        #pragma unroll
        for (int ks = 0; ks < 4; ks++) {
            const float* e0 = sf[2 * ks];
            const float* e1 = sf[2 * ks + 1];
            #pragma unroll
            for (int q = 0; q < 2; q++) {
                const float* e = q ? e1 : e0;
                float hx0 = __bfloat162float(__float2bfloat16(e[0]));
                float hx1 = __bfloat162float(__float2bfloat16(e[1]));
                float hx2 = __bfloat162float(__float2bfloat16(e[2]));
                float hx3 = __bfloat162float(__float2bfloat16(e[3]));
                phi[ks][2 * q]     = pack_bf16(e[0], e[1]);
                phi[ks][2 * q + 1] = pack_bf16(e[2], e[3]);
                plo[ks][2 * q]     = pack_bf16(e[0] - hx0, e[1] - hx1);
                plo[ks][2 * q + 1] = pack_bf16(e[2] - hx2, e[3] - hx3);
            }
        }

        // ---- O += Phat . Vthat^T  (3 terms, term-outer issue order) ----
        #pragma unroll
        for (int ks = 0; ks < 4; ks++) {
            uint32_t bhi[4][4], blo[4][4];
            #pragma unroll
            for (int g = 0; g < 4; g++) {
                const uint32_t bd = vB +
                    (uint32_t)((g * 16 + lrow) * ASTRB + ks * 32) + lcolb;
                LDSM_X4(bhi[g][0], bhi[g][1], bhi[g][2], bhi[g][3], bd);
                LDSM_X4(blo[g][0], blo[g][1], blo[g][2], blo[g][3], bd + 128);
            }
            #pragma unroll
            for (int term = 0; term < 3; term++)
                #pragma unroll
                for (int g = 0; g < 4; g++)
                    #pragma unroll
                    for (int hh = 0; hh < 2; hh++) {
                        const int t = 2 * g + hh;
                        const uint32_t* pf = (term == 2) ? plo[ks] : phi[ks];
                        const uint32_t* bf = (term == 1) ? blo[g]  : bhi[g];
                        MMA_BF16(oacc[t][0], oacc[t][1], oacc[t][2], oacc[t][3],
                                 pf[0], pf[1], pf[2], pf[3],
                                 bf[hh], bf[2 + hh]);
                    }
        }

        if (kt < qt) {
            CP_WAIT(0);
            __syncthreads();
        }
    }

    const float inv0 = 1.0f / l0;
    const float inv1 = 1.0f / l1;
    const int r0g = q0 + rl0;
    const int r1g = q0 + rl1;
    const size_t pb0 = ((size_t)b * TSEQ + r0g) * K2 + h * HD;
    const size_t pb1 = ((size_t)b * TSEQ + r1g) * K2 + h * HD;
    #pragma unroll
    for (int t = 0; t < 8; t++) {
        const int cg = t * 8 + 2 * (lane & 3);
        const float v00 = oacc[t][0] * inv0, v01 = oacc[t][1] * inv0;
        const float v10 = oacc[t][2] * inv1, v11 = oacc[t][3] * inv1;
        const uint32_t h0 = pack_bf16(v00, v01);
        const uint32_t h1 = pack_bf16(v10, v11);
        __nv_bfloat162 h0b = *reinterpret_cast<const __nv_bfloat162*>(&h0);
        __nv_bfloat162 h1b = *reinterpret_cast<const __nv_bfloat162*>(&h1);
        const uint32_t l0p = pack_bf16(v00 - __bfloat162float(h0b.x),
                                       v01 - __bfloat162float(h0b.y));
        const uint32_t l1p = pack_bf16(v10 - __bfloat162float(h1b.x),
                                       v11 - __bfloat162float(h1b.y));
        *reinterpret_cast<uint32_t*>(&outp[pb0 + cg])        = h0;
        *reinterpret_cast<uint32_t*>(&outp[pb0 + CDIM + cg]) = l0p;
        *reinterpret_cast<uint32_t*>(&outp[pb1 + cg])        = h1;
        *reinterpret_cast<uint32_t*>(&outp[pb1 + CDIM + cg]) = l1p;
    }
}

// ---------------------------------------------------------------------------
// Launch
// ---------------------------------------------------------------------------
extern "C" void kernel_launch(void* const* d_in, const int* in_sizes, int n_in,
                              void* d_out, int out_size)
{
    const float* x     = (const float*)d_in[0];
    const float* Wqkv  = (const float*)d_in[1];
    const float* bqkv  = (const float*)d_in[2];
    const float* Wproj = (const float*)d_in[3];
    const float* bproj = (const float*)d_in[4];
    float* out = (float*)d_out;

    __nv_bfloat16 *ahat, *bqkvp, *bprojp, *qp, *kp, *vp;
    cudaGetSymbolAddress((void**)&ahat,   g_ahat);
    cudaGetSymbolAddress((void**)&bqkvp,  g_bqkv);
    cudaGetSymbolAddress((void**)&bprojp, g_bproj);
    cudaGetSymbolAddress((void**)&qp,     g_qpack);
    cudaGetSymbolAddress((void**)&kp,     g_kpack);
    cudaGetSymbolAddress((void**)&vp,     g_vpack);

    cudaFuncSetAttribute(attn_mma,
                         cudaFuncAttributeMaxDynamicSharedMemorySize, ATTN_SMEM);
    cudaFuncSetAttribute(gemm_mma,
                         cudaFuncAttributeMaxDynamicSharedMemorySize, GEMM_SMEM);
    cudaFuncSetAttribute(gemm_qkv,
                         cudaFuncAttributeMaxDynamicSharedMemorySize, GEMM_SMEM);

    // Pack weights -> [N, 2K] = [hi|lo]
    {
        dim3 bb(32, 8);
        convert_split_wT<<<dim3(THREEC / 32, CDIM / 32), bb>>>(Wqkv, bqkvp, CDIM, THREEC);
        convert_split_wT<<<dim3(CDIM / 32, CDIM / 32), bb>>>(Wproj, bprojp, CDIM, CDIM);
    }

    // 1) Pack x; QKV GEMM writes packed Q/K/V directly
    convert_split_act<<<(MROWS * CDIM + 255) / 256, 256>>>(x, ahat, MROWS * CDIM, CDIM);
    gemm_qkv<<<dim3(THREEC / 128, MROWS / 128), GEMM_THREADS, GEMM_SMEM>>>(
        ahat, bqkvp, bqkv, qp, kp, vp);

    // 2) Pipelined attention -> packed proj input
    attn_mma<<<dim3(TSEQ / 64, NH, BATCH), 128, ATTN_SMEM>>>(qp, kp, vp, ahat);

    // 3) Output projection
    gemm_mma<<<dim3(CDIM / 128, MROWS / 128), GEMM_THREADS, GEMM_SMEM>>>(
        ahat, bprojp, bproj, out, MROWS, CDIM);
}

// round 13
// speedup vs baseline: 1.0603x; 1.0226x over previous
#include <cuda_runtime.h>
#include <cuda_bf16.h>
#include <math.h>
#include <cstdint>

// Problem constants
#define BATCH 2
#define TSEQ  2048
#define CDIM  1024
#define NH    16
#define HD    64
#define THREEC (3*CDIM)
#define MROWS (BATCH*TSEQ)   // 4096
#define K2    (2*CDIM)       // [hi|lo] packed K = 2048

// ---------------------------------------------------------------------------
// Scratch (__device__ globals; allocation-free rule)
// ---------------------------------------------------------------------------
__device__ __nv_bfloat16 g_ahat[(size_t)MROWS * K2];       // packed activations
__device__ __nv_bfloat16 g_bqkv[(size_t)THREEC * K2];      // packed Wqkv^T
__device__ __nv_bfloat16 g_bproj[(size_t)CDIM * K2];       // packed Wproj^T
// Pre-split attention operands (written directly by the QKV GEMM epilogue)
__device__ __nv_bfloat16 g_qpack[(size_t)BATCH * NH * TSEQ * 128];
__device__ __nv_bfloat16 g_kpack[(size_t)BATCH * NH * TSEQ * 128];
__device__ __nv_bfloat16 g_vpack[(size_t)BATCH * NH * HD * 2 * TSEQ];

// ---------------------------------------------------------------------------
// Helpers (base-ISA only: cp.async / ldmatrix / mma.sync)
// ---------------------------------------------------------------------------
__device__ __forceinline__ uint32_t smem_u32(const void* p) {
    uint32_t a;
    asm("{ .reg .u64 t; cvta.to.shared.u64 t, %1; cvt.u32.u64 %0, t; }"
        : "=r"(a) : "l"(p));
    return a;
}
#define CP_ASYNC16(smaddr, gptr) \
    asm volatile("cp.async.cg.shared.global [%0], [%1], 16;" \
                 :: "r"(smaddr), "l"(gptr))
#define CP_COMMIT() asm volatile("cp.async.commit_group;" ::: "memory")
#define CP_WAIT(n)  asm volatile("cp.async.wait_group %0;" :: "n"(n) : "memory")

#define LDSM_X4(r0, r1, r2, r3, addr) \
    asm volatile("ldmatrix.sync.aligned.m8n8.x4.shared.b16 {%0,%1,%2,%3}, [%4];" \
                 : "=r"(r0), "=r"(r1), "=r"(r2), "=r"(r3) : "r"(addr))

#define MMA_BF16(c0, c1, c2, c3, a0, a1, a2, a3, b0, b1) \
    asm volatile("mma.sync.aligned.m16n8k16.row.col.f32.bf16.bf16.f32 " \
                 "{%0,%1,%2,%3}, {%4,%5,%6,%7}, {%8,%9}, {%0,%1,%2,%3};" \
                 : "+f"(c0), "+f"(c1), "+f"(c2), "+f"(c3) \
                 : "r"(a0), "r"(a1), "r"(a2), "r"(a3), "r"(b0), "r"(b1))

__device__ __forceinline__ uint32_t pack_bf16(float x, float y) {
    __nv_bfloat162 h = __floats2bfloat162_rn(x, y);
    return *reinterpret_cast<uint32_t*>(&h);
}

// ---------------------------------------------------------------------------
// Vectorized split-convert activations: A[M,K] fp32 -> Ahat[M,2K] = [hi | lo]
// 4 elements per thread: float4 load, two uint2 stores (8B-aligned).
// ---------------------------------------------------------------------------
__global__ void convert_split_act4(const float4* __restrict__ in,
                                   __nv_bfloat16* __restrict__ out,
                                   int MK4, int K)
{
    const int idx = blockIdx.x * blockDim.x + threadIdx.x;
    if (idx >= MK4) return;
    const int kq = K >> 2;
    const int m  = idx / kq;
    const int k  = (idx - m * kq) << 2;
    const float4 v = in[idx];

    const uint32_t hi01 = pack_bf16(v.x, v.y);
    const uint32_t hi23 = pack_bf16(v.z, v.w);
    const __nv_bfloat162 h01 = *reinterpret_cast<const __nv_bfloat162*>(&hi01);
    const __nv_bfloat162 h23 = *reinterpret_cast<const __nv_bfloat162*>(&hi23);
    const uint32_t lo01 = pack_bf16(v.x - __bfloat162float(h01.x),
                                    v.y - __bfloat162float(h01.y));
    const uint32_t lo23 = pack_bf16(v.z - __bfloat162float(h23.x),
                                    v.w - __bfloat162float(h23.y));

    const size_t base = (size_t)m * (2 * K);
    *reinterpret_cast<uint2*>(&out[base + k])     = make_uint2(hi01, hi23);
    *reinterpret_cast<uint2*>(&out[base + K + k]) = make_uint2(lo01, lo23);
}

// ---------------------------------------------------------------------------
// Transpose + split-convert weights: W[K,N] fp32 -> Bhat[N,2K] bf16 = [hi|lo]
// ---------------------------------------------------------------------------
__global__ void convert_split_wT(const float* __restrict__ W,
                                 __nv_bfloat16* __restrict__ out, int K, int N)
{
    __shared__ float t[32][33];
    const int tx = threadIdx.x, ty = threadIdx.y;   // block (32, 8)
    const int n0 = blockIdx.x * 32, k0 = blockIdx.y * 32;
    #pragma unroll
    for (int j = 0; j < 4; j++)
        t[ty + j * 8][tx] = W[(size_t)(k0 + ty + j * 8) * N + n0 + tx];
    __syncthreads();
    #pragma unroll
    for (int j = 0; j < 4; j++) {
        const int nn = ty + j * 8;
        float v = t[tx][nn];
        __nv_bfloat16 hi = __float2bfloat16(v);
        __nv_bfloat16 lo = __float2bfloat16(v - __bfloat162float(hi));
        size_t base = (size_t)(n0 + nn) * (2 * K) + k0 + tx;
        out[base]     = hi;
        out[base + K] = lo;
    }
}

// ---------------------------------------------------------------------------
// Shared GEMM mainloop config: 128x128 CTA tile, 8 warps (256 thr),
// 32x64 warp tile. [hi|lo] + register 3-term split. R8-measured-best order.
// ---------------------------------------------------------------------------
#define GBK   32
#define NSTG  (CDIM / GBK)            // 32
#define ROWB  144
#define STAGE_BYTES (128 * ROWB)      // 18432
#define STAGES 2
#define GEMM_SMEM (2 * STAGES * STAGE_BYTES)   // 73728 bytes
#define GEMM_THREADS 256

#define GEMM_MAINLOOP(Aptr, Bptr)                                              \
    extern __shared__ __align__(16) unsigned char gsm[];                       \
    const int tid  = threadIdx.x;                                              \
    const int wid  = tid >> 5;                                                 \
    const int lane = tid & 31;                                                 \
    const int wm   = wid & 3;                                                  \
    const int wn   = wid >> 2;                                                 \
    const int row0 = blockIdx.y * 128;                                         \
    const int col0 = blockIdx.x * 128;                                         \
    const uint32_t smA_b = smem_u32(gsm);                                      \
    const uint32_t smB_b = smA_b + STAGES * STAGE_BYTES;                       \
    const __nv_bfloat16* Arow = (Aptr) + (size_t)row0 * K2;                    \
    const __nv_bfloat16* Brow = (Bptr) + (size_t)col0 * K2;                    \
    auto load_stage = [&](int s, int buf) {                                    \
        const int k0 = s * GBK;                                                \
        const uint32_t ao = smA_b + buf * STAGE_BYTES;                         \
        const uint32_t bo = smB_b + buf * STAGE_BYTES;                         \
        _Pragma("unroll")                                                      \
        for (int i = 0; i < 4; i++) {                                          \
            const int idx = i * 256 + tid;                                     \
            const int r   = idx >> 3;                                          \
            const int c   = idx & 7;                                           \
            const int cc  = c & 3;                                             \
            const int gofs = (c < 4) ? (k0 + cc * 8) : (CDIM + k0 + cc * 8);   \
            const uint32_t so = (uint32_t)(r * ROWB + cc * 16 + ((c < 4) ? 0 : 64)); \
            CP_ASYNC16(ao + so, Arow + (size_t)r * K2 + gofs);                 \
            CP_ASYNC16(bo + so, Brow + (size_t)r * K2 + gofs);                 \
        }                                                                      \
    };                                                                         \
    float acc[2][8][4];                                                        \
    _Pragma("unroll")                                                          \
    for (int i = 0; i < 2; i++)                                                \
        _Pragma("unroll")                                                      \
        for (int j = 0; j < 8; j++)                                            \
            _Pragma("unroll")                                                  \
            for (int k = 0; k < 4; k++) acc[i][j][k] = 0.f;                    \
    const int lrow = lane & 15;                                                \
    const int lcol = (lane >> 4) << 4;                                         \
    load_stage(0, 0);                                                          \
    CP_COMMIT();                                                               \
    for (int s = 0; s < NSTG; s++) {                                           \
        CP_WAIT(0);                                                            \
        __syncthreads();                                                       \
        if (s + 1 < NSTG) { load_stage(s + 1, (s + 1) & 1); CP_COMMIT(); }     \
        const int buf = s & 1;                                                 \
        const uint32_t aB = smA_b + buf * STAGE_BYTES;                         \
        const uint32_t bB = smB_b + buf * STAGE_BYTES;                         \
        _Pragma("unroll")                                                      \
        for (int ks = 0; ks < 2; ks++) {                                       \
            uint32_t ahi[2][4], alo[2][4], bhi[4][4], blo[4][4];               \
            _Pragma("unroll")                                                  \
            for (int fm = 0; fm < 2; fm++) {                                   \
                const uint32_t ad = aB +                                       \
                    (uint32_t)((wm * 32 + fm * 16 + lrow) * ROWB + ks * 32) + lcol; \
                LDSM_X4(ahi[fm][0], ahi[fm][1], ahi[fm][2], ahi[fm][3], ad);   \
                LDSM_X4(alo[fm][0], alo[fm][1], alo[fm][2], alo[fm][3], ad + 64); \
            }                                                                  \
            _Pragma("unroll")                                                  \
            for (int g = 0; g < 4; g++) {                                      \
                const uint32_t bd = bB +                                       \
                    (uint32_t)((wn * 64 + g * 16 + lrow) * ROWB + ks * 32) + lcol; \
                LDSM_X4(bhi[g][0], bhi[g][1], bhi[g][2], bhi[g][3], bd);       \
                LDSM_X4(blo[g][0], blo[g][1], blo[g][2], blo[g][3], bd + 64);  \
            }                                                                  \
            _Pragma("unroll")                                                  \
            for (int fm = 0; fm < 2; fm++)                                     \
                _Pragma("unroll")                                              \
                for (int fn = 0; fn < 8; fn++) {                               \
                    const int g = fn >> 1, h = fn & 1;                         \
                    MMA_BF16(acc[fm][fn][0], acc[fm][fn][1],                   \
                             acc[fm][fn][2], acc[fm][fn][3],                   \
                             ahi[fm][0], ahi[fm][1], ahi[fm][2], ahi[fm][3],   \
                             bhi[g][h], bhi[g][2 + h]);                        \
                    MMA_BF16(acc[fm][fn][0], acc[fm][fn][1],                   \
                             acc[fm][fn][2], acc[fm][fn][3],                   \
                             ahi[fm][0], ahi[fm][1], ahi[fm][2], ahi[fm][3],   \
                             blo[g][h], blo[g][2 + h]);                        \
                    MMA_BF16(acc[fm][fn][0], acc[fm][fn][1],                   \
                             acc[fm][fn][2], acc[fm][fn][3],                   \
                             alo[fm][0], alo[fm][1], alo[fm][2], alo[fm][3],   \
                             bhi[g][h], bhi[g][2 + h]);                        \
                }                                                              \
        }                                                                      \
    }

// ---------------------------------------------------------------------------
// Proj GEMM: plain fp32 output + bias
// ---------------------------------------------------------------------------
__global__ __launch_bounds__(GEMM_THREADS) void gemm_mma(
    const __nv_bfloat16* __restrict__ A,
    const __nv_bfloat16* __restrict__ B,
    const float* __restrict__ bias,
    float* __restrict__ C, int M, int N)
{
    GEMM_MAINLOOP(A, B)

    const int erow = lane >> 2;
    const int ecol = (lane & 3) << 1;
    #pragma unroll
    for (int fm = 0; fm < 2; fm++) {
        const int r0g = row0 + wm * 32 + fm * 16 + erow;
        #pragma unroll
        for (int fn = 0; fn < 8; fn++) {
            const int cg = col0 + wn * 64 + fn * 8 + ecol;
            const float b0 = bias[cg], b1 = bias[cg + 1];
            float2 v0 = make_float2(acc[fm][fn][0] + b0, acc[fm][fn][1] + b1);
            float2 v1 = make_float2(acc[fm][fn][2] + b0, acc[fm][fn][3] + b1);
            *reinterpret_cast<float2*>(&C[(size_t)r0g * N + cg]) = v0;
            *reinterpret_cast<float2*>(&C[(size_t)(r0g + 8) * N + cg]) = v1;
        }
    }
}

// ---------------------------------------------------------------------------
// QKV GEMM with fused pack epilogue (writes qpack/kpack/vpack directly)
// ---------------------------------------------------------------------------
__global__ __launch_bounds__(GEMM_THREADS) void gemm_qkv(
    const __nv_bfloat16* __restrict__ A,
    const __nv_bfloat16* __restrict__ B,
    const float* __restrict__ bias,
    __nv_bfloat16* __restrict__ qpack,
    __nv_bfloat16* __restrict__ kpack,
    __nv_bfloat16* __restrict__ vpack)
{
    GEMM_MAINLOOP(A, B)

    const int erow = lane >> 2;
    const int ecol = (lane & 3) << 1;
    const int sec  = col0 >> 10;                      // 0=Q 1=K 2=V
    const int hh   = ((col0 & 1023) >> 6) + wn;       // head (per-warp constant)
    const float scale = (sec == 0) ? 0.125f : 1.0f;

    #pragma unroll
    for (int fm = 0; fm < 2; fm++) {
        const int t0g = row0 + wm * 32 + fm * 16 + erow;
        const int bidx = t0g >> 11;
        const int bh   = bidx * NH + hh;
        const int tl0  = t0g & 2047;
        const int tl1  = tl0 + 8;
        #pragma unroll
        for (int fn = 0; fn < 8; fn++) {
            const int cg = col0 + wn * 64 + fn * 8 + ecol;
            const int d  = (cg & 63);
            const float b0 = bias[cg], b1 = bias[cg + 1];
            const float v00 = (acc[fm][fn][0] + b0) * scale;
            const float v01 = (acc[fm][fn][1] + b1) * scale;
            const float v10 = (acc[fm][fn][2] + b0) * scale;
            const float v11 = (acc[fm][fn][3] + b1) * scale;

            const uint32_t h0 = pack_bf16(v00, v01);
            const uint32_t h1 = pack_bf16(v10, v11);
            const __nv_bfloat162 h0b = *reinterpret_cast<const __nv_bfloat162*>(&h0);
            const __nv_bfloat162 h1b = *reinterpret_cast<const __nv_bfloat162*>(&h1);
            const uint32_t l0 = pack_bf16(v00 - __bfloat162float(h0b.x),
                                          v01 - __bfloat162float(h0b.y));
            const uint32_t l1 = pack_bf16(v10 - __bfloat162float(h1b.x),
                                          v11 - __bfloat162float(h1b.y));

            if (sec < 2) {
                __nv_bfloat16* dst = (sec == 0) ? qpack : kpack;
                const size_t r0 = ((size_t)bh * TSEQ + tl0) * 128 + d;
                const size_t r1 = ((size_t)bh * TSEQ + tl1) * 128 + d;
                *reinterpret_cast<uint32_t*>(&dst[r0])      = h0;
                *reinterpret_cast<uint32_t*>(&dst[r0 + 64]) = l0;
                *reinterpret_cast<uint32_t*>(&dst[r1])      = h1;
                *reinterpret_cast<uint32_t*>(&dst[r1 + 64]) = l1;
            } else {
                #pragma unroll
                for (int dd = 0; dd < 2; dd++) {
                    const size_t vb = ((size_t)bh * HD + d + dd) * (2 * TSEQ);
                    const size_t c0 = vb + (tl0 >> 6) * 128 + (tl0 & 63);
                    const size_t c1 = vb + (tl1 >> 6) * 128 + (tl1 & 63);
                    const float e0 = dd ? v01 : v00;
                    const float e1 = dd ? v11 : v10;
                    const __nv_bfloat16 e0h = __float2bfloat16(e0);
                    const __nv_bfloat16 e1h = __float2bfloat16(e1);
                    vpack[c0]      = e0h;
                    vpack[c0 + 64] = __float2bfloat16(e0 - __bfloat162float(e0h));
                    vpack[c1]      = e1h;
                    vpack[c1 + 64] = __float2bfloat16(e1 - __bfloat162float(e1h));
                }
            }
        }
    }
}

// ---------------------------------------------------------------------------
// Tensor-core causal flash attention, full 3-term split on S and PV
// (R8 numerics and issue order — measured best).
// ---------------------------------------------------------------------------
#define ASTR  136
#define ASTRB 272
#define TILEB (64 * ASTRB)                 // 17408
#define ATTN_SMEM (4 * TILEB)              // 69632 bytes

__global__ __launch_bounds__(128) void attn_mma(
    const __nv_bfloat16* __restrict__ qpack,
    const __nv_bfloat16* __restrict__ kpack,
    const __nv_bfloat16* __restrict__ vpack,
    __nv_bfloat16* __restrict__ outp)
{
    extern __shared__ __align__(16) unsigned char smraw[];

    const int qt   = (gridDim.x - 1) - blockIdx.x;
    const int h    = blockIdx.y;
    const int b    = blockIdx.z;
    const int tid  = threadIdx.x;
    const int wid  = tid >> 5;
    const int lane = tid & 31;
    const int q0   = qt * 64;
    const int bh   = b * NH + h;

    const uint32_t KsB = smem_u32(smraw);
    const uint32_t QsB = KsB + TILEB;            // Q staged in K-buf1
    const uint32_t VsB = KsB + 2 * TILEB;

    const __nv_bfloat16* qrows = qpack + ((size_t)bh * TSEQ + q0) * 128;
    const __nv_bfloat16* krows = kpack + (size_t)bh * TSEQ * 128;
    const __nv_bfloat16* vrows = vpack + (size_t)bh * HD * (2 * TSEQ);

    auto load_kv = [&](int kt, int buf) {
        const uint32_t kdst = KsB + buf * TILEB;
        const uint32_t vdst = VsB + buf * TILEB;
        #pragma unroll
        for (int i = 0; i < 8; i++) {
            const int idx = i * 128 + tid;
            const int r = idx >> 4;
            const int c = idx & 15;
            CP_ASYNC16(kdst + (uint32_t)(r * ASTRB + c * 16),
                       krows + ((size_t)(kt * 64 + r)) * 128 + c * 8);
            CP_ASYNC16(vdst + (uint32_t)(r * ASTRB + c * 16),
                       vrows + (size_t)r * (2 * TSEQ) + kt * 128 + c * 8);
        }
    };

    #pragma unroll
    for (int i = 0; i < 8; i++) {
        const int idx = i * 128 + tid;
        const int r = idx >> 4;
        const int c = idx & 15;
        CP_ASYNC16(QsB + (uint32_t)(r * ASTRB + c * 16),
                   qrows + (size_t)r * 128 + c * 8);
    }
    load_kv(0, 0);
    CP_COMMIT();
    CP_WAIT(0);
    __syncthreads();

    const int lrow  = lane & 15;
    const int lcolb = (lane >> 4) << 4;
    uint32_t ahi[4][4], alo[4][4];
    #pragma unroll
    for (int ks = 0; ks < 4; ks++) {
        const uint32_t ad = QsB + (uint32_t)((16 * wid + lrow) * ASTRB + ks * 32) + lcolb;
        LDSM_X4(ahi[ks][0], ahi[ks][1], ahi[ks][2], ahi[ks][3], ad);
        LDSM_X4(alo[ks][0], alo[ks][1], alo[ks][2], alo[ks][3], ad + 128);
    }
    __syncthreads();

    float oacc[8][4];
    #pragma unroll
    for (int t = 0; t < 8; t++)
        #pragma unroll
        for (int j = 0; j < 4; j++) oacc[t][j] = 0.f;
    float m0r = -1.0e30f, m1r = -1.0e30f, l0 = 0.f, l1 = 0.f;

    const int rl0 = 16 * wid + (lane >> 2);
    const int rl1 = rl0 + 8;

    for (int kt = 0; kt <= qt; kt++) {
        if (kt < qt) { load_kv(kt + 1, (kt + 1) & 1); CP_COMMIT(); }

        const uint32_t kB = KsB + (kt & 1) * TILEB;
        const uint32_t vB = VsB + (kt & 1) * TILEB;

        float sf[8][4];
        #pragma unroll
        for (int t = 0; t < 8; t++)
            #pragma unroll
            for (int j = 0; j < 4; j++) sf[t][j] = 0.f;

        #pragma unroll
        for (int ks = 0; ks < 4; ks++) {
            uint32_t bhi[4][4], blo[4][4];
            #pragma unroll
            for (int g = 0; g < 4; g++) {
                const uint32_t bd = kB +
                    (uint32_t)((g * 16 + lrow) * ASTRB + ks * 32) + lcolb;
                LDSM_X4(bhi[g][0], bhi[g][1], bhi[g][2], bhi[g][3], bd);
                LDSM_X4(blo[g][0], blo[g][1], blo[g][2], blo[g][3], bd + 128);
            }
            #pragma unroll
            for (int g = 0; g < 4; g++)
                #pragma unroll
                for (int hh = 0; hh < 2; hh++) {
                    const int t = 2 * g + hh;
                    MMA_BF16(sf[t][0], sf[t][1], sf[t][2], sf[t][3],
                             ahi[ks][0], ahi[ks][1], ahi[ks][2], ahi[ks][3],
                             bhi[g][hh], bhi[g][2 + hh]);
                    MMA_BF16(sf[t][0], sf[t][1], sf[t][2], sf[t][3],
                             ahi[ks][0], ahi[ks][1], ahi[ks][2], ahi[ks][3],
                             blo[g][hh], blo[g][2 + hh]);
                    MMA_BF16(sf[t][0], sf[t][1], sf[t][2], sf[t][3],
                             alo[ks][0], alo[ks][1], alo[ks][2], alo[ks][3],
                             bhi[g][hh], bhi[g][2 + hh]);
                }
        }

        if (kt == qt) {
            #pragma unroll
            for (int t = 0; t < 8; t++) {
                const int c = t * 8 + 2 * (lane & 3);
                if (c     > rl0) sf[t][0] = -1.0e30f;
                if (c + 1 > rl0) sf[t][1] = -1.0e30f;
                if (c     > rl1) sf[t][2] = -1.0e30f;
                if (c + 1 > rl1) sf[t][3] = -1.0e30f;
            }
        }

        float rm0 = -1.0e30f, rm1 = -1.0e30f;
        #pragma unroll
        for (int t = 0; t < 8; t++) {
            rm0 = fmaxf(rm0, fmaxf(sf[t][0], sf[t][1]));
            rm1 = fmaxf(rm1, fmaxf(sf[t][2], sf[t][3]));
        }
        rm0 = fmaxf(rm0, __shfl_xor_sync(0xffffffffu, rm0, 1));
        rm0 = fmaxf(rm0, __shfl_xor_sync(0xffffffffu, rm0, 2));
        rm1 = fmaxf(rm1, __shfl_xor_sync(0xffffffffu, rm1, 1));
        rm1 = fmaxf(rm1, __shfl_xor_sync(0xffffffffu, rm1, 2));
        const float mn0 = fmaxf(m0r, rm0);
        const float mn1 = fmaxf(m1r, rm1);

        float sum0 = 0.f, sum1 = 0.f;
        #pragma unroll
        for (int t = 0; t < 8; t++) {
            sf[t][0] = __expf(sf[t][0] - mn0);
            sf[t][1] = __expf(sf[t][1] - mn0);
            sf[t][2] = __expf(sf[t][2] - mn1);
            sf[t][3] = __expf(sf[t][3] - mn1);
            sum0 += sf[t][0] + sf[t][1];
            sum1 += sf[t][2] + sf[t][3];
        }
        sum0 += __shfl_xor_sync(0xffffffffu, sum0, 1);
        sum0 += __shfl_xor_sync(0xffffffffu, sum0, 2);
        sum1 += __shfl_xor_sync(0xffffffffu, sum1, 1);
        sum1 += __shfl_xor_sync(0xffffffffu, sum1, 2);

        const float al0 = __expf(m0r - mn0);
        const float al1 = __expf(m1r - mn1);
        l0 = l0 * al0 + sum0;  m0r = mn0;
        l1 = l1 * al1 + sum1;  m1r = mn1;
        #pragma unroll
        for (int t = 0; t < 8; t++) {
            oacc[t][0] *= al0; oacc[t][1] *= al0;
            oacc[t][2] *= al1; oacc[t][3] *= al1;
        }

        uint32_t phi[4][4], plo[4][4];
        #pragma unroll
        for (int ks = 0; ks < 4; ks++) {
            const float* e0 = sf[2 * ks];
            const float* e1 = sf[2 * ks + 1];
            #pragma unroll
            for (int q = 0; q < 2; q++) {
                const float* e = q ? e1 : e0;
                float hx0 = __bfloat162float(__float2bfloat16(e[0]));
                float hx1 = __bfloat162float(__float2bfloat16(e[1]));
                float hx2 = __bfloat162float(__float2bfloat16(e[2]));
                float hx3 = __bfloat162float(__float2bfloat16(e[3]));
                phi[ks][2 * q]     = pack_bf16(e[0], e[1]);
                phi[ks][2 * q + 1] = pack_bf16(e[2], e[3]);
                plo[ks][2 * q]     = pack_bf16(e[0] - hx0, e[1] - hx1);
                plo[ks][2 * q + 1] = pack_bf16(e[2] - hx2, e[3] - hx3);
            }
        }

        #pragma unroll
        for (int ks = 0; ks < 4; ks++) {
            uint32_t bhi[4][4], blo[4][4];
            #pragma unroll
            for (int g = 0; g < 4; g++) {
                const uint32_t bd = vB +
                    (uint32_t)((g * 16 + lrow) * ASTRB + ks * 32) + lcolb;
                LDSM_X4(bhi[g][0], bhi[g][1], bhi[g][2], bhi[g][3], bd);
                LDSM_X4(blo[g][0], blo[g][1], blo[g][2], blo[g][3], bd + 128);
            }
            #pragma unroll
            for (int g = 0; g < 4; g++)
                #pragma unroll
                for (int hh = 0; hh < 2; hh++) {
                    const int t = 2 * g + hh;
                    MMA_BF16(oacc[t][0], oacc[t][1], oacc[t][2], oacc[t][3],
                             phi[ks][0], phi[ks][1], phi[ks][2], phi[ks][3],
                             bhi[g][hh], bhi[g][2 + hh]);
                    MMA_BF16(oacc[t][0], oacc[t][1], oacc[t][2], oacc[t][3],
                             phi[ks][0], phi[ks][1], phi[ks][2], phi[ks][3],
                             blo[g][hh], blo[g][2 + hh]);
                    MMA_BF16(oacc[t][0], oacc[t][1], oacc[t][2], oacc[t][3],
                             plo[ks][0], plo[ks][1], plo[ks][2], plo[ks][3],
                             bhi[g][hh], bhi[g][2 + hh]);
                }
        }

        if (kt < qt) {
            CP_WAIT(0);
            __syncthreads();
        }
    }

    const float inv0 = 1.0f / l0;
    const float inv1 = 1.0f / l1;
    const int r0g = q0 + rl0;
    const int r1g = q0 + rl1;
    const size_t pb0 = ((size_t)b * TSEQ + r0g) * K2 + h * HD;
    const size_t pb1 = ((size_t)b * TSEQ + r1g) * K2 + h * HD;
    #pragma unroll
    for (int t = 0; t < 8; t++) {
        const int cg = t * 8 + 2 * (lane & 3);
        const float v00 = oacc[t][0] * inv0, v01 = oacc[t][1] * inv0;
        const float v10 = oacc[t][2] * inv1, v11 = oacc[t][3] * inv1;
        const uint32_t h0 = pack_bf16(v00, v01);
        const uint32_t h1 = pack_bf16(v10, v11);
        __nv_bfloat162 h0b = *reinterpret_cast<const __nv_bfloat162*>(&h0);
        __nv_bfloat162 h1b = *reinterpret_cast<const __nv_bfloat162*>(&h1);
        const uint32_t l0p = pack_bf16(v00 - __bfloat162float(h0b.x),
                                       v01 - __bfloat162float(h0b.y));
        const uint32_t l1p = pack_bf16(v10 - __bfloat162float(h1b.x),
                                       v11 - __bfloat162float(h1b.y));
        *reinterpret_cast<uint32_t*>(&outp[pb0 + cg])        = h0;
        *reinterpret_cast<uint32_t*>(&outp[pb0 + CDIM + cg]) = l0p;
        *reinterpret_cast<uint32_t*>(&outp[pb1 + cg])        = h1;
        *reinterpret_cast<uint32_t*>(&outp[pb1 + CDIM + cg]) = l1p;
    }
}

// ---------------------------------------------------------------------------
// Launch
// ---------------------------------------------------------------------------
extern "C" void kernel_launch(void* const* d_in, const int* in_sizes, int n_in,
                              void* d_out, int out_size)
{
    const float* x     = (const float*)d_in[0];
    const float* Wqkv  = (const float*)d_in[1];
    const float* bqkv  = (const float*)d_in[2];
    const float* Wproj = (const float*)d_in[3];
    const float* bproj = (const float*)d_in[4];
    float* out = (float*)d_out;

    __nv_bfloat16 *ahat, *bqkvp, *bprojp, *qp, *kp, *vp;
    cudaGetSymbolAddress((void**)&ahat,   g_ahat);
    cudaGetSymbolAddress((void**)&bqkvp,  g_bqkv);
    cudaGetSymbolAddress((void**)&bprojp, g_bproj);
    cudaGetSymbolAddress((void**)&qp,     g_qpack);
    cudaGetSymbolAddress((void**)&kp,     g_kpack);
    cudaGetSymbolAddress((void**)&vp,     g_vpack);

    cudaFuncSetAttribute(attn_mma,
                         cudaFuncAttributeMaxDynamicSharedMemorySize, ATTN_SMEM);
    cudaFuncSetAttribute(gemm_mma,
                         cudaFuncAttributeMaxDynamicSharedMemorySize, GEMM_SMEM);
    cudaFuncSetAttribute(gemm_qkv,
                         cudaFuncAttributeMaxDynamicSharedMemorySize, GEMM_SMEM);

    // Pack weights -> [N, 2K] = [hi|lo]
    {
        dim3 bb(32, 8);
        convert_split_wT<<<dim3(THREEC / 32, CDIM / 32), bb>>>(Wqkv, bqkvp, CDIM, THREEC);
        convert_split_wT<<<dim3(CDIM / 32, CDIM / 32), bb>>>(Wproj, bprojp, CDIM, CDIM);
    }

    // 1) Pack x (vectorized); QKV GEMM writes packed Q/K/V directly
    {
        const int mk4 = MROWS * CDIM / 4;
        convert_split_act4<<<(mk4 + 255) / 256, 256>>>(
            (const float4*)x, ahat, mk4, CDIM);
    }
    gemm_qkv<<<dim3(THREEC / 128, MROWS / 128), GEMM_THREADS, GEMM_SMEM>>>(
        ahat, bqkvp, bqkv, qp, kp, vp);

    // 2) Pipelined attention -> packed proj input
    attn_mma<<<dim3(TSEQ / 64, NH, BATCH), 128, ATTN_SMEM>>>(qp, kp, vp, ahat);

    // 3) Output projection
    gemm_mma<<<dim3(CDIM / 128, MROWS / 128), GEMM_THREADS, GEMM_SMEM>>>(
        ahat, bprojp, bproj, out, MROWS, CDIM);
}

// round 14
// speedup vs baseline: 1.4658x; 1.3824x over previous
#include <cuda_runtime.h>
#include <cuda_fp16.h>
#include <math.h>
#include <cstdint>

// Problem constants
#define BATCH 2
#define TSEQ  2048
#define CDIM  1024
#define NH    16
#define HD    64
#define THREEC (3*CDIM)
#define MROWS (BATCH*TSEQ)   // 4096
#define KB2   (2*CDIM)       // B-side [hi|lo] packed K = 2048

// ---------------------------------------------------------------------------
// Scratch (__device__ globals; allocation-free rule)
// ---------------------------------------------------------------------------
__device__ __half g_ahat[(size_t)MROWS * CDIM];     // A operand: hi-only fp16
__device__ __half g_bqkv[(size_t)THREEC * KB2];     // Wqkv^T packed [hi|lo]
__device__ __half g_bproj[(size_t)CDIM * KB2];      // Wproj^T packed [hi|lo]
// Attention operands (written directly by the QKV GEMM epilogue)
__device__ __half g_qpack[(size_t)BATCH * NH * TSEQ * 64];    // Q hi-only
__device__ __half g_kpack[(size_t)BATCH * NH * TSEQ * 128];   // K [hi|lo]
__device__ __half g_vpack[(size_t)BATCH * NH * HD * 2 * TSEQ];// V^T [hi|lo]

// ---------------------------------------------------------------------------
// Helpers (base-ISA only: cp.async / ldmatrix / mma.sync)
// ---------------------------------------------------------------------------
__device__ __forceinline__ uint32_t smem_u32(const void* p) {
    uint32_t a;
    asm("{ .reg .u64 t; cvta.to.shared.u64 t, %1; cvt.u32.u64 %0, t; }"
        : "=r"(a) : "l"(p));
    return a;
}
#define CP_ASYNC16(smaddr, gptr) \
    asm volatile("cp.async.cg.shared.global [%0], [%1], 16;" \
                 :: "r"(smaddr), "l"(gptr))
#define CP_COMMIT() asm volatile("cp.async.commit_group;" ::: "memory")
#define CP_WAIT(n)  asm volatile("cp.async.wait_group %0;" :: "n"(n) : "memory")

#define LDSM_X4(r0, r1, r2, r3, addr) \
    asm volatile("ldmatrix.sync.aligned.m8n8.x4.shared.b16 {%0,%1,%2,%3}, [%4];" \
                 : "=r"(r0), "=r"(r1), "=r"(r2), "=r"(r3) : "r"(addr))

#define MMA_F16(c0, c1, c2, c3, a0, a1, a2, a3, b0, b1) \
    asm volatile("mma.sync.aligned.m16n8k16.row.col.f32.f16.f16.f32 " \
                 "{%0,%1,%2,%3}, {%4,%5,%6,%7}, {%8,%9}, {%0,%1,%2,%3};" \
                 : "+f"(c0), "+f"(c1), "+f"(c2), "+f"(c3) \
                 : "r"(a0), "r"(a1), "r"(a2), "r"(a3), "r"(b0), "r"(b1))

__device__ __forceinline__ uint32_t pack_half(float x, float y) {
    __half2 h = __floats2half2_rn(x, y);
    return *reinterpret_cast<uint32_t*>(&h);
}

// ---------------------------------------------------------------------------
// Convert activations: A[M,K] fp32 -> Ahat[M,K] fp16 (hi only), vectorized.
// ---------------------------------------------------------------------------
__global__ void convert_act_f16(const float4* __restrict__ in,
                                uint2* __restrict__ out, int MK4)
{
    const int idx = blockIdx.x * blockDim.x + threadIdx.x;
    if (idx >= MK4) return;
    const float4 v = in[idx];
    out[idx] = make_uint2(pack_half(v.x, v.y), pack_half(v.z, v.w));
}

// ---------------------------------------------------------------------------
// Transpose + split weights: W[K,N] fp32 -> Bhat[N,2K] fp16 = [hi|lo]
// ---------------------------------------------------------------------------
__global__ void convert_split_wT(const float* __restrict__ W,
                                 __half* __restrict__ out, int K, int N)
{
    __shared__ float t[32][33];
    const int tx = threadIdx.x, ty = threadIdx.y;   // block (32, 8)
    const int n0 = blockIdx.x * 32, k0 = blockIdx.y * 32;
    #pragma unroll
    for (int j = 0; j < 4; j++)
        t[ty + j * 8][tx] = W[(size_t)(k0 + ty + j * 8) * N + n0 + tx];
    __syncthreads();
    #pragma unroll
    for (int j = 0; j < 4; j++) {
        const int nn = ty + j * 8;
        float v = t[tx][nn];
        __half hi = __float2half_rn(v);
        __half lo = __float2half_rn(v - __half2float(hi));
        size_t base = (size_t)(n0 + nn) * (2 * K) + k0 + tx;
        out[base]     = hi;
        out[base + K] = lo;
    }
}

// ---------------------------------------------------------------------------
// GEMM: 128x128 CTA tile, 8 warps (256 thr), 32x64 warp tile.
// A = fp16 hi-only [M, CDIM]; B = fp16 [N, 2*CDIM] [hi|lo].
// 2-term MMA: Ahi.Bhi + Ahi.Blo  (drops Alo.Bhi, ~2^-12 relative).
// ---------------------------------------------------------------------------
#define GBK   32
#define NSTG  (CDIM / GBK)            // 32
#define AROWB 80                      // 64B hi data + 16 pad
#define BROWB 144                     // 64B hi + 64B lo + 16 pad
#define STAGE_A (128 * AROWB)         // 10240
#define STAGE_B (128 * BROWB)         // 18432
#define STAGES 2
#define GEMM_SMEM (STAGES * (STAGE_A + STAGE_B))   // 57344
#define GEMM_THREADS 256

#define GEMM_MAINLOOP(Aptr, Bptr)                                              \
    extern __shared__ __align__(16) unsigned char gsm[];                       \
    const int tid  = threadIdx.x;                                              \
    const int wid  = tid >> 5;                                                 \
    const int lane = tid & 31;                                                 \
    const int wm   = wid & 3;                                                  \
    const int wn   = wid >> 2;                                                 \
    const int row0 = blockIdx.y * 128;                                         \
    const int col0 = blockIdx.x * 128;                                         \
    const uint32_t smA_b = smem_u32(gsm);                                      \
    const uint32_t smB_b = smA_b + STAGES * STAGE_A;                           \
    const __half* Arow = (Aptr) + (size_t)row0 * CDIM;                         \
    const __half* Brow = (Bptr) + (size_t)col0 * KB2;                          \
    auto load_stage = [&](int s, int buf) {                                    \
        const int k0 = s * GBK;                                                \
        const uint32_t ao = smA_b + buf * STAGE_A;                             \
        const uint32_t bo = smB_b + buf * STAGE_B;                             \
        _Pragma("unroll")                                                      \
        for (int i = 0; i < 2; i++) {                                          \
            const int idx = i * 256 + tid;       /* 512 A chunks */            \
            const int r = idx >> 2, c = idx & 3;                               \
            CP_ASYNC16(ao + (uint32_t)(r * AROWB + c * 16),                    \
                       Arow + (size_t)r * CDIM + k0 + c * 8);                  \
        }                                                                      \
        _Pragma("unroll")                                                      \
        for (int i = 0; i < 4; i++) {                                          \
            const int idx = i * 256 + tid;       /* 1024 B chunks */           \
            const int r = idx >> 3, c = idx & 7, cc = c & 3;                   \
            const int gofs = (c < 4) ? (k0 + cc * 8) : (CDIM + k0 + cc * 8);   \
            const uint32_t so = (uint32_t)(r * BROWB + cc * 16 + ((c < 4) ? 0 : 64)); \
            CP_ASYNC16(bo + so, Brow + (size_t)r * KB2 + gofs);                \
        }                                                                      \
    };                                                                         \
    float acc[2][8][4];                                                        \
    _Pragma("unroll")                                                          \
    for (int i = 0; i < 2; i++)                                                \
        _Pragma("unroll")                                                      \
        for (int j = 0; j < 8; j++)                                            \
            _Pragma("unroll")                                                  \
            for (int k = 0; k < 4; k++) acc[i][j][k] = 0.f;                    \
    const int lrow = lane & 15;                                                \
    const int lcol = (lane >> 4) << 4;                                         \
    load_stage(0, 0);                                                          \
    CP_COMMIT();                                                               \
    for (int s = 0; s < NSTG; s++) {                                           \
        CP_WAIT(0);                                                            \
        __syncthreads();                                                       \
        if (s + 1 < NSTG) { load_stage(s + 1, (s + 1) & 1); CP_COMMIT(); }     \
        const int buf = s & 1;                                                 \
        const uint32_t aB = smA_b + buf * STAGE_A;                             \
        const uint32_t bB = smB_b + buf * STAGE_B;                             \
        _Pragma("unroll")                                                      \
        for (int ks = 0; ks < 2; ks++) {                                       \
            uint32_t ah[2][4], bhi[4][4], blo[4][4];                           \
            _Pragma("unroll")                                                  \
            for (int fm = 0; fm < 2; fm++) {                                   \
                const uint32_t ad = aB +                                       \
                    (uint32_t)((wm * 32 + fm * 16 + lrow) * AROWB + ks * 32) + lcol; \
                LDSM_X4(ah[fm][0], ah[fm][1], ah[fm][2], ah[fm][3], ad);       \
            }                                                                  \
            _Pragma("unroll")                                                  \
            for (int g = 0; g < 4; g++) {                                      \
                const uint32_t bd = bB +                                       \
                    (uint32_t)((wn * 64 + g * 16 + lrow) * BROWB + ks * 32) + lcol; \
                LDSM_X4(bhi[g][0], bhi[g][1], bhi[g][2], bhi[g][3], bd);       \
                LDSM_X4(blo[g][0], blo[g][1], blo[g][2], blo[g][3], bd + 64);  \
            }                                                                  \
            _Pragma("unroll")                                                  \
            for (int fm = 0; fm < 2; fm++)                                     \
                _Pragma("unroll")                                              \
                for (int fn = 0; fn < 8; fn++) {                               \
                    const int g = fn >> 1, h = fn & 1;                         \
                    MMA_F16(acc[fm][fn][0], acc[fm][fn][1],                    \
                            acc[fm][fn][2], acc[fm][fn][3],                    \
                            ah[fm][0], ah[fm][1], ah[fm][2], ah[fm][3],        \
                            bhi[g][h], bhi[g][2 + h]);                         \
                    MMA_F16(acc[fm][fn][0], acc[fm][fn][1],                    \
                            acc[fm][fn][2], acc[fm][fn][3],                    \
                            ah[fm][0], ah[fm][1], ah[fm][2], ah[fm][3],        \
                            blo[g][h], blo[g][2 + h]);                         \
                }                                                              \
        }                                                                      \
    }

// ---------------------------------------------------------------------------
// Proj GEMM: plain fp32 output + bias
// ---------------------------------------------------------------------------
__global__ __launch_bounds__(GEMM_THREADS) void gemm_mma(
    const __half* __restrict__ A,
    const __half* __restrict__ B,
    const float* __restrict__ bias,
    float* __restrict__ C, int M, int N)
{
    GEMM_MAINLOOP(A, B)

    const int erow = lane >> 2;
    const int ecol = (lane & 3) << 1;
    #pragma unroll
    for (int fm = 0; fm < 2; fm++) {
        const int r0g = row0 + wm * 32 + fm * 16 + erow;
        #pragma unroll
        for (int fn = 0; fn < 8; fn++) {
            const int cg = col0 + wn * 64 + fn * 8 + ecol;
            const float b0 = bias[cg], b1 = bias[cg + 1];
            float2 v0 = make_float2(acc[fm][fn][0] + b0, acc[fm][fn][1] + b1);
            float2 v1 = make_float2(acc[fm][fn][2] + b0, acc[fm][fn][3] + b1);
            *reinterpret_cast<float2*>(&C[(size_t)r0g * N + cg]) = v0;
            *reinterpret_cast<float2*>(&C[(size_t)(r0g + 8) * N + cg]) = v1;
        }
    }
}

// ---------------------------------------------------------------------------
// QKV GEMM with fused pack epilogue:
//   Q -> hi-only fp16 [bh][t][64]  (pre-scaled by 1/8)
//   K -> [bh][t][hi 64|lo 64] fp16
//   V -> transposed [bh][d][per-64-tile: hi|lo] fp16
// ---------------------------------------------------------------------------
__global__ __launch_bounds__(GEMM_THREADS) void gemm_qkv(
    const __half* __restrict__ A,
    const __half* __restrict__ B,
    const float* __restrict__ bias,
    __half* __restrict__ qpack,
    __half* __restrict__ kpack,
    __half* __restrict__ vpack)
{
    GEMM_MAINLOOP(A, B)

    const int erow = lane >> 2;
    const int ecol = (lane & 3) << 1;
    const int sec  = col0 >> 10;                      // 0=Q 1=K 2=V
    const int hh   = ((col0 & 1023) >> 6) + wn;       // head (per-warp constant)
    const float scale = (sec == 0) ? 0.125f : 1.0f;

    #pragma unroll
    for (int fm = 0; fm < 2; fm++) {
        const int t0g = row0 + wm * 32 + fm * 16 + erow;
        const int bidx = t0g >> 11;
        const int bh   = bidx * NH + hh;
        const int tl0  = t0g & 2047;
        const int tl1  = tl0 + 8;
        #pragma unroll
        for (int fn = 0; fn < 8; fn++) {
            const int cg = col0 + wn * 64 + fn * 8 + ecol;
            const int d  = (cg & 63);
            const float b0 = bias[cg], b1 = bias[cg + 1];
            const float v00 = (acc[fm][fn][0] + b0) * scale;
            const float v01 = (acc[fm][fn][1] + b1) * scale;
            const float v10 = (acc[fm][fn][2] + b0) * scale;
            const float v11 = (acc[fm][fn][3] + b1) * scale;

            const uint32_t h0 = pack_half(v00, v01);
            const uint32_t h1 = pack_half(v10, v11);

            if (sec == 0) {
                const size_t r0 = ((size_t)bh * TSEQ + tl0) * 64 + d;
                const size_t r1 = ((size_t)bh * TSEQ + tl1) * 64 + d;
                *reinterpret_cast<uint32_t*>(&qpack[r0]) = h0;
                *reinterpret_cast<uint32_t*>(&qpack[r1]) = h1;
            } else if (sec == 1) {
                const __half2 h0h = *reinterpret_cast<const __half2*>(&h0);
                const __half2 h1h = *reinterpret_cast<const __half2*>(&h1);
                const uint32_t l0 = pack_half(v00 - __low2float(h0h),
                                              v01 - __high2float(h0h));
                const uint32_t l1 = pack_half(v10 - __low2float(h1h),
                                              v11 - __high2float(h1h));
                const size_t r0 = ((size_t)bh * TSEQ + tl0) * 128 + d;
                const size_t r1 = ((size_t)bh * TSEQ + tl1) * 128 + d;
                *reinterpret_cast<uint32_t*>(&kpack[r0])      = h0;
                *reinterpret_cast<uint32_t*>(&kpack[r0 + 64]) = l0;
                *reinterpret_cast<uint32_t*>(&kpack[r1])      = h1;
                *reinterpret_cast<uint32_t*>(&kpack[r1 + 64]) = l1;
            } else {
                #pragma unroll
                for (int dd = 0; dd < 2; dd++) {
                    const size_t vb = ((size_t)bh * HD + d + dd) * (2 * TSEQ);
                    const size_t c0 = vb + (tl0 >> 6) * 128 + (tl0 & 63);
                    const size_t c1 = vb + (tl1 >> 6) * 128 + (tl1 & 63);
                    const float e0 = dd ? v01 : v00;
                    const float e1 = dd ? v11 : v10;
                    const __half e0h = __float2half_rn(e0);
                    const __half e1h = __float2half_rn(e1);
                    vpack[c0]      = e0h;
                    vpack[c0 + 64] = __float2half_rn(e0 - __half2float(e0h));
                    vpack[c1]      = e1h;
                    vpack[c1 + 64] = __float2half_rn(e1 - __half2float(e1h));
                }
            }
        }
    }
}

// ---------------------------------------------------------------------------
// Causal flash attention, fp16 2-term: S = Qhi.(Khi+Klo), O += Phi.(Vhi+Vlo)
// Q hi-only (144B rows, overlaid on K-buf1); K/V split (272B rows).
// ---------------------------------------------------------------------------
#define ASTRB 272
#define QROWB 144
#define TILEB (64 * ASTRB)                 // 17408
#define ATTN_SMEM (4 * TILEB)              // 69632 bytes

__global__ __launch_bounds__(128) void attn_mma(
    const __half* __restrict__ qpack,
    const __half* __restrict__ kpack,
    const __half* __restrict__ vpack,
    __half* __restrict__ outp)
{
    extern __shared__ __align__(16) unsigned char smraw[];

    const int qt   = (gridDim.x - 1) - blockIdx.x;
    const int h    = blockIdx.y;
    const int b    = blockIdx.z;
    const int tid  = threadIdx.x;
    const int wid  = tid >> 5;
    const int lane = tid & 31;
    const int q0   = qt * 64;
    const int bh   = b * NH + h;

    const uint32_t KsB = smem_u32(smraw);
    const uint32_t QsB = KsB + TILEB;            // Q staged in K-buf1
    const uint32_t VsB = KsB + 2 * TILEB;

    const __half* qrows = qpack + ((size_t)bh * TSEQ + q0) * 64;
    const __half* krows = kpack + (size_t)bh * TSEQ * 128;
    const __half* vrows = vpack + (size_t)bh * HD * (2 * TSEQ);

    auto load_kv = [&](int kt, int buf) {
        const uint32_t kdst = KsB + buf * TILEB;
        const uint32_t vdst = VsB + buf * TILEB;
        #pragma unroll
        for (int i = 0; i < 8; i++) {
            const int idx = i * 128 + tid;
            const int r = idx >> 4;
            const int c = idx & 15;
            CP_ASYNC16(kdst + (uint32_t)(r * ASTRB + c * 16),
                       krows + ((size_t)(kt * 64 + r)) * 128 + c * 8);
            CP_ASYNC16(vdst + (uint32_t)(r * ASTRB + c * 16),
                       vrows + (size_t)r * (2 * TSEQ) + kt * 128 + c * 8);
        }
    };

    // Prologue: Q (hi-only, 512 chunks) + first K/V tile
    #pragma unroll
    for (int i = 0; i < 4; i++) {
        const int idx = i * 128 + tid;
        const int r = idx >> 3;
        const int c = idx & 7;
        CP_ASYNC16(QsB + (uint32_t)(r * QROWB + c * 16),
                   qrows + (size_t)r * 64 + c * 8);
    }
    load_kv(0, 0);
    CP_COMMIT();
    CP_WAIT(0);
    __syncthreads();

    const int lrow  = lane & 15;
    const int lcolb = (lane >> 4) << 4;
    uint32_t ah[4][4];
    #pragma unroll
    for (int ks = 0; ks < 4; ks++) {
        const uint32_t ad = QsB + (uint32_t)((16 * wid + lrow) * QROWB + ks * 32) + lcolb;
        LDSM_X4(ah[ks][0], ah[ks][1], ah[ks][2], ah[ks][3], ad);
    }
    __syncthreads();   // Q region free before kt=1 prefetch reuses K-buf1

    float oacc[8][4];
    #pragma unroll
    for (int t = 0; t < 8; t++)
        #pragma unroll
        for (int j = 0; j < 4; j++) oacc[t][j] = 0.f;
    float m0r = -1.0e30f, m1r = -1.0e30f, l0 = 0.f, l1 = 0.f;

    const int rl0 = 16 * wid + (lane >> 2);
    const int rl1 = rl0 + 8;

    for (int kt = 0; kt <= qt; kt++) {
        if (kt < qt) { load_kv(kt + 1, (kt + 1) & 1); CP_COMMIT(); }

        const uint32_t kB = KsB + (kt & 1) * TILEB;
        const uint32_t vB = VsB + (kt & 1) * TILEB;

        float sf[8][4];
        #pragma unroll
        for (int t = 0; t < 8; t++)
            #pragma unroll
            for (int j = 0; j < 4; j++) sf[t][j] = 0.f;

        #pragma unroll
        for (int ks = 0; ks < 4; ks++) {
            uint32_t bhi[4][4], blo[4][4];
            #pragma unroll
            for (int g = 0; g < 4; g++) {
                const uint32_t bd = kB +
                    (uint32_t)((g * 16 + lrow) * ASTRB + ks * 32) + lcolb;
                LDSM_X4(bhi[g][0], bhi[g][1], bhi[g][2], bhi[g][3], bd);
                LDSM_X4(blo[g][0], blo[g][1], blo[g][2], blo[g][3], bd + 128);
            }
            #pragma unroll
            for (int g = 0; g < 4; g++)
                #pragma unroll
                for (int hh = 0; hh < 2; hh++) {
                    const int t = 2 * g + hh;
                    MMA_F16(sf[t][0], sf[t][1], sf[t][2], sf[t][3],
                            ah[ks][0], ah[ks][1], ah[ks][2], ah[ks][3],
                            bhi[g][hh], bhi[g][2 + hh]);
                    MMA_F16(sf[t][0], sf[t][1], sf[t][2], sf[t][3],
                            ah[ks][0], ah[ks][1], ah[ks][2], ah[ks][3],
                            blo[g][hh], blo[g][2 + hh]);
                }
        }

        if (kt == qt) {
            #pragma unroll
            for (int t = 0; t < 8; t++) {
                const int c = t * 8 + 2 * (lane & 3);
                if (c     > rl0) sf[t][0] = -1.0e30f;
                if (c + 1 > rl0) sf[t][1] = -1.0e30f;
                if (c     > rl1) sf[t][2] = -1.0e30f;
                if (c + 1 > rl1) sf[t][3] = -1.0e30f;
            }
        }

        float rm0 = -1.0e30f, rm1 = -1.0e30f;
        #pragma unroll
        for (int t = 0; t < 8; t++) {
            rm0 = fmaxf(rm0, fmaxf(sf[t][0], sf[t][1]));
            rm1 = fmaxf(rm1, fmaxf(sf[t][2], sf[t][3]));
        }
        rm0 = fmaxf(rm0, __shfl_xor_sync(0xffffffffu, rm0, 1));
        rm0 = fmaxf(rm0, __shfl_xor_sync(0xffffffffu, rm0, 2));
        rm1 = fmaxf(rm1, __shfl_xor_sync(0xffffffffu, rm1, 1));
        rm1 = fmaxf(rm1, __shfl_xor_sync(0xffffffffu, rm1, 2));
        const float mn0 = fmaxf(m0r, rm0);
        const float mn1 = fmaxf(m1r, rm1);

        float sum0 = 0.f, sum1 = 0.f;
        #pragma unroll
        for (int t = 0; t < 8; t++) {
            sf[t][0] = __expf(sf[t][0] - mn0);
            sf[t][1] = __expf(sf[t][1] - mn0);
            sf[t][2] = __expf(sf[t][2] - mn1);
            sf[t][3] = __expf(sf[t][3] - mn1);
            sum0 += sf[t][0] + sf[t][1];
            sum1 += sf[t][2] + sf[t][3];
        }
        sum0 += __shfl_xor_sync(0xffffffffu, sum0, 1);
        sum0 += __shfl_xor_sync(0xffffffffu, sum0, 2);
        sum1 += __shfl_xor_sync(0xffffffffu, sum1, 1);
        sum1 += __shfl_xor_sync(0xffffffffu, sum1, 2);

        const float al0 = __expf(m0r - mn0);
        const float al1 = __expf(m1r - mn1);
        l0 = l0 * al0 + sum0;  m0r = mn0;
        l1 = l1 * al1 + sum1;  m1r = mn1;
        #pragma unroll
        for (int t = 0; t < 8; t++) {
            oacc[t][0] *= al0; oacc[t][1] *= al0;
            oacc[t][2] *= al1; oacc[t][3] *= al1;
        }

        // ---- P fragments: fp16 hi (2^-12 quantization) ----
        uint32_t phi[4][4];
        #pragma unroll
        for (int ks = 0; ks < 4; ks++) {
            const float* e0 = sf[2 * ks];
            const float* e1 = sf[2 * ks + 1];
            phi[ks][0] = pack_half(e0[0], e0[1]);
            phi[ks][1] = pack_half(e0[2], e0[3]);
            phi[ks][2] = pack_half(e1[0], e1[1]);
            phi[ks][3] = pack_half(e1[2], e1[3]);
        }

        // ---- O += Phi . (Vhi + Vlo) ----
        #pragma unroll
        for (int ks = 0; ks < 4; ks++) {
            uint32_t bhi[4][4], blo[4][4];
            #pragma unroll
            for (int g = 0; g < 4; g++) {
                const uint32_t bd = vB +
                    (uint32_t)((g * 16 + lrow) * ASTRB + ks * 32) + lcolb;
                LDSM_X4(bhi[g][0], bhi[g][1], bhi[g][2], bhi[g][3], bd);
                LDSM_X4(blo[g][0], blo[g][1], blo[g][2], blo[g][3], bd + 128);
            }
            #pragma unroll
            for (int g = 0; g < 4; g++)
                #pragma unroll
                for (int hh = 0; hh < 2; hh++) {
                    const int t = 2 * g + hh;
                    MMA_F16(oacc[t][0], oacc[t][1], oacc[t][2], oacc[t][3],
                            phi[ks][0], phi[ks][1], phi[ks][2], phi[ks][3],
                            bhi[g][hh], bhi[g][2 + hh]);
                    MMA_F16(oacc[t][0], oacc[t][1], oacc[t][2], oacc[t][3],
                            phi[ks][0], phi[ks][1], phi[ks][2], phi[ks][3],
                            blo[g][hh], blo[g][2 + hh]);
                }
        }

        if (kt < qt) {
            CP_WAIT(0);
            __syncthreads();
        }
    }

    // ---- Epilogue: hi-only fp16 proj input [M, CDIM] ----
    const float inv0 = 1.0f / l0;
    const float inv1 = 1.0f / l1;
    const int r0g = q0 + rl0;
    const int r1g = q0 + rl1;
    const size_t pb0 = ((size_t)b * TSEQ + r0g) * CDIM + h * HD;
    const size_t pb1 = ((size_t)b * TSEQ + r1g) * CDIM + h * HD;
    #pragma unroll
    for (int t = 0; t < 8; t++) {
        const int cg = t * 8 + 2 * (lane & 3);
        *reinterpret_cast<uint32_t*>(&outp[pb0 + cg]) =
            pack_half(oacc[t][0] * inv0, oacc[t][1] * inv0);
        *reinterpret_cast<uint32_t*>(&outp[pb1 + cg]) =
            pack_half(oacc[t][2] * inv1, oacc[t][3] * inv1);
    }
}

// ---------------------------------------------------------------------------
// Launch
// ---------------------------------------------------------------------------
extern "C" void kernel_launch(void* const* d_in, const int* in_sizes, int n_in,
                              void* d_out, int out_size)
{
    const float* x     = (const float*)d_in[0];
    const float* Wqkv  = (const float*)d_in[1];
    const float* bqkv  = (const float*)d_in[2];
    const float* Wproj = (const float*)d_in[3];
    const float* bproj = (const float*)d_in[4];
    float* out = (float*)d_out;

    __half *ahat, *bqkvp, *bprojp, *qp, *kp, *vp;
    cudaGetSymbolAddress((void**)&ahat,   g_ahat);
    cudaGetSymbolAddress((void**)&bqkvp,  g_bqkv);
    cudaGetSymbolAddress((void**)&bprojp, g_bproj);
    cudaGetSymbolAddress((void**)&qp,     g_qpack);
    cudaGetSymbolAddress((void**)&kp,     g_kpack);
    cudaGetSymbolAddress((void**)&vp,     g_vpack);

    cudaFuncSetAttribute(attn_mma,
                         cudaFuncAttributeMaxDynamicSharedMemorySize, ATTN_SMEM);
    cudaFuncSetAttribute(gemm_mma,
                         cudaFuncAttributeMaxDynamicSharedMemorySize, GEMM_SMEM);
    cudaFuncSetAttribute(gemm_qkv,
                         cudaFuncAttributeMaxDynamicSharedMemorySize, GEMM_SMEM);

    // Pack weights -> [N, 2K] fp16 [hi|lo]
    {
        dim3 bb(32, 8);
        convert_split_wT<<<dim3(THREEC / 32, CDIM / 32), bb>>>(Wqkv, bqkvp, CDIM, THREEC);
        convert_split_wT<<<dim3(CDIM / 32, CDIM / 32), bb>>>(Wproj, bprojp, CDIM, CDIM);
    }

    // 1) Pack x (hi-only fp16); QKV GEMM writes packed Q/K/V directly
    {
        const int mk4 = MROWS * CDIM / 4;
        convert_act_f16<<<(mk4 + 255) / 256, 256>>>(
            (const float4*)x, (uint2*)ahat, mk4);
    }
    gemm_qkv<<<dim3(THREEC / 128, MROWS / 128), GEMM_THREADS, GEMM_SMEM>>>(
        ahat, bqkvp, bqkv, qp, kp, vp);

    // 2) Pipelined attention -> hi-only proj input
    attn_mma<<<dim3(TSEQ / 64, NH, BATCH), 128, ATTN_SMEM>>>(qp, kp, vp, ahat);

    // 3) Output projection
    gemm_mma<<<dim3(CDIM / 128, MROWS / 128), GEMM_THREADS, GEMM_SMEM>>>(
        ahat, bprojp, bproj, out, MROWS, CDIM);
}

// round 15
// speedup vs baseline: 1.7715x; 1.2085x over previous
#include <cuda_runtime.h>
#include <cuda_fp16.h>
#include <math.h>
#include <cstdint>

// Problem constants
#define BATCH 2
#define TSEQ  2048
#define CDIM  1024
#define NH    16
#define HD    64
#define THREEC (3*CDIM)
#define MROWS (BATCH*TSEQ)   // 4096
#define KB2   (2*CDIM)       // B-side [hi|lo] packed K = 2048

// ---------------------------------------------------------------------------
// Scratch (__device__ globals; allocation-free rule)
// ---------------------------------------------------------------------------
__device__ __half g_ahat[(size_t)MROWS * CDIM];     // A operand: hi-only fp16
__device__ __half g_bqkv[(size_t)THREEC * KB2];     // Wqkv^T packed [hi|lo]
__device__ __half g_bproj[(size_t)CDIM * KB2];      // Wproj^T packed [hi|lo]
// Attention operands (hi-only fp16, written by the QKV GEMM epilogue)
__device__ __half g_qpack[(size_t)BATCH * NH * TSEQ * 64];   // [bh][t][d]
__device__ __half g_kpack[(size_t)BATCH * NH * TSEQ * 64];   // [bh][t][d]
__device__ __half g_vpack[(size_t)BATCH * NH * HD * TSEQ];   // [bh][d][t]

// ---------------------------------------------------------------------------
// Helpers (base-ISA only: cp.async / ldmatrix / mma.sync)
// ---------------------------------------------------------------------------
__device__ __forceinline__ uint32_t smem_u32(const void* p) {
    uint32_t a;
    asm("{ .reg .u64 t; cvta.to.shared.u64 t, %1; cvt.u32.u64 %0, t; }"
        : "=r"(a) : "l"(p));
    return a;
}
#define CP_ASYNC16(smaddr, gptr) \
    asm volatile("cp.async.cg.shared.global [%0], [%1], 16;" \
                 :: "r"(smaddr), "l"(gptr))
#define CP_COMMIT() asm volatile("cp.async.commit_group;" ::: "memory")
#define CP_WAIT(n)  asm volatile("cp.async.wait_group %0;" :: "n"(n) : "memory")

#define LDSM_X4(r0, r1, r2, r3, addr) \
    asm volatile("ldmatrix.sync.aligned.m8n8.x4.shared.b16 {%0,%1,%2,%3}, [%4];" \
                 : "=r"(r0), "=r"(r1), "=r"(r2), "=r"(r3) : "r"(addr))

#define MMA_F16(c0, c1, c2, c3, a0, a1, a2, a3, b0, b1) \
    asm volatile("mma.sync.aligned.m16n8k16.row.col.f32.f16.f16.f32 " \
                 "{%0,%1,%2,%3}, {%4,%5,%6,%7}, {%8,%9}, {%0,%1,%2,%3};" \
                 : "+f"(c0), "+f"(c1), "+f"(c2), "+f"(c3) \
                 : "r"(a0), "r"(a1), "r"(a2), "r"(a3), "r"(b0), "r"(b1))

__device__ __forceinline__ uint32_t pack_half(float x, float y) {
    __half2 h = __floats2half2_rn(x, y);
    return *reinterpret_cast<uint32_t*>(&h);
}

// ---------------------------------------------------------------------------
// Convert activations: A[M,K] fp32 -> Ahat[M,K] fp16 (hi only), vectorized.
// ---------------------------------------------------------------------------
__global__ void convert_act_f16(const float4* __restrict__ in,
                                uint2* __restrict__ out, int MK4)
{
    const int idx = blockIdx.x * blockDim.x + threadIdx.x;
    if (idx >= MK4) return;
    const float4 v = in[idx];
    out[idx] = make_uint2(pack_half(v.x, v.y), pack_half(v.z, v.w));
}

// ---------------------------------------------------------------------------
// Transpose + split weights: W[K,N] fp32 -> Bhat[N,2K] fp16 = [hi|lo]
// ---------------------------------------------------------------------------
__global__ void convert_split_wT(const float* __restrict__ W,
                                 __half* __restrict__ out, int K, int N)
{
    __shared__ float t[32][33];
    const int tx = threadIdx.x, ty = threadIdx.y;   // block (32, 8)
    const int n0 = blockIdx.x * 32, k0 = blockIdx.y * 32;
    #pragma unroll
    for (int j = 0; j < 4; j++)
        t[ty + j * 8][tx] = W[(size_t)(k0 + ty + j * 8) * N + n0 + tx];
    __syncthreads();
    #pragma unroll
    for (int j = 0; j < 4; j++) {
        const int nn = ty + j * 8;
        float v = t[tx][nn];
        __half hi = __float2half_rn(v);
        __half lo = __float2half_rn(v - __half2float(hi));
        size_t base = (size_t)(n0 + nn) * (2 * K) + k0 + tx;
        out[base]     = hi;
        out[base + K] = lo;
    }
}

// ---------------------------------------------------------------------------
// GEMM: 128x128 CTA tile, 8 warps (256 thr), 32x64 warp tile.
// A = fp16 hi-only [M, CDIM]; B = fp16 [N, 2*CDIM] [hi|lo].
// 2-term MMA: Ahi.Bhi + Ahi.Blo  (drops Alo.Bhi, ~2^-12 relative).
// ---------------------------------------------------------------------------
#define GBK   32
#define NSTG  (CDIM / GBK)            // 32
#define AROWB 80
#define BROWB 144
#define STAGE_A (128 * AROWB)         // 10240
#define STAGE_B (128 * BROWB)         // 18432
#define STAGES 2
#define GEMM_SMEM (STAGES * (STAGE_A + STAGE_B))   // 57344
#define GEMM_THREADS 256

#define GEMM_MAINLOOP(Aptr, Bptr)                                              \
    extern __shared__ __align__(16) unsigned char gsm[];                       \
    const int tid  = threadIdx.x;                                              \
    const int wid  = tid >> 5;                                                 \
    const int lane = tid & 31;                                                 \
    const int wm   = wid & 3;                                                  \
    const int wn   = wid >> 2;                                                 \
    const int row0 = blockIdx.y * 128;                                         \
    const int col0 = blockIdx.x * 128;                                         \
    const uint32_t smA_b = smem_u32(gsm);                                      \
    const uint32_t smB_b = smA_b + STAGES * STAGE_A;                           \
    const __half* Arow = (Aptr) + (size_t)row0 * CDIM;                         \
    const __half* Brow = (Bptr) + (size_t)col0 * KB2;                          \
    auto load_stage = [&](int s, int buf) {                                    \
        const int k0 = s * GBK;                                                \
        const uint32_t ao = smA_b + buf * STAGE_A;                             \
        const uint32_t bo = smB_b + buf * STAGE_B;                             \
        _Pragma("unroll")                                                      \
        for (int i = 0; i < 2; i++) {                                          \
            const int idx = i * 256 + tid;                                     \
            const int r = idx >> 2, c = idx & 3;                               \
            CP_ASYNC16(ao + (uint32_t)(r * AROWB + c * 16),                    \
                       Arow + (size_t)r * CDIM + k0 + c * 8);                  \
        }                                                                      \
        _Pragma("unroll")                                                      \
        for (int i = 0; i < 4; i++) {                                          \
            const int idx = i * 256 + tid;                                     \
            const int r = idx >> 3, c = idx & 7, cc = c & 3;                   \
            const int gofs = (c < 4) ? (k0 + cc * 8) : (CDIM + k0 + cc * 8);   \
            const uint32_t so = (uint32_t)(r * BROWB + cc * 16 + ((c < 4) ? 0 : 64)); \
            CP_ASYNC16(bo + so, Brow + (size_t)r * KB2 + gofs);                \
        }                                                                      \
    };                                                                         \
    float acc[2][8][4];                                                        \
    _Pragma("unroll")                                                          \
    for (int i = 0; i < 2; i++)                                                \
        _Pragma("unroll")                                                      \
        for (int j = 0; j < 8; j++)                                            \
            _Pragma("unroll")                                                  \
            for (int k = 0; k < 4; k++) acc[i][j][k] = 0.f;                    \
    const int lrow = lane & 15;                                                \
    const int lcol = (lane >> 4) << 4;                                         \
    load_stage(0, 0);                                                          \
    CP_COMMIT();                                                               \
    for (int s = 0; s < NSTG; s++) {                                           \
        CP_WAIT(0);                                                            \
        __syncthreads();                                                       \
        if (s + 1 < NSTG) { load_stage(s + 1, (s + 1) & 1); CP_COMMIT(); }     \
        const int buf = s & 1;                                                 \
        const uint32_t aB = smA_b + buf * STAGE_A;                             \
        const uint32_t bB = smB_b + buf * STAGE_B;                             \
        _Pragma("unroll")                                                      \
        for (int ks = 0; ks < 2; ks++) {                                       \
            uint32_t ah[2][4], bhi[4][4], blo[4][4];                           \
            _Pragma("unroll")                                                  \
            for (int fm = 0; fm < 2; fm++) {                                   \
                const uint32_t ad = aB +                                       \
                    (uint32_t)((wm * 32 + fm * 16 + lrow) * AROWB + ks * 32) + lcol; \
                LDSM_X4(ah[fm][0], ah[fm][1], ah[fm][2], ah[fm][3], ad);       \
            }                                                                  \
            _Pragma("unroll")                                                  \
            for (int g = 0; g < 4; g++) {                                      \
                const uint32_t bd = bB +                                       \
                    (uint32_t)((wn * 64 + g * 16 + lrow) * BROWB + ks * 32) + lcol; \
                LDSM_X4(bhi[g][0], bhi[g][1], bhi[g][2], bhi[g][3], bd);       \
                LDSM_X4(blo[g][0], blo[g][1], blo[g][2], blo[g][3], bd + 64);  \
            }                                                                  \
            _Pragma("unroll")                                                  \
            for (int fm = 0; fm < 2; fm++)                                     \
                _Pragma("unroll")                                              \
                for (int fn = 0; fn < 8; fn++) {                               \
                    const int g = fn >> 1, h = fn & 1;                         \
                    MMA_F16(acc[fm][fn][0], acc[fm][fn][1],                    \
                            acc[fm][fn][2], acc[fm][fn][3],                    \
                            ah[fm][0], ah[fm][1], ah[fm][2], ah[fm][3],        \
                            bhi[g][h], bhi[g][2 + h]);                         \
                    MMA_F16(acc[fm][fn][0], acc[fm][fn][1],                    \
                            acc[fm][fn][2], acc[fm][fn][3],                    \
                            ah[fm][0], ah[fm][1], ah[fm][2], ah[fm][3],        \
                            blo[g][h], blo[g][2 + h]);                         \
                }                                                              \
        }                                                                      \
    }

// ---------------------------------------------------------------------------
// Proj GEMM: plain fp32 output + bias
// ---------------------------------------------------------------------------
__global__ __launch_bounds__(GEMM_THREADS) void gemm_mma(
    const __half* __restrict__ A,
    const __half* __restrict__ B,
    const float* __restrict__ bias,
    float* __restrict__ C, int M, int N)
{
    GEMM_MAINLOOP(A, B)

    const int erow = lane >> 2;
    const int ecol = (lane & 3) << 1;
    #pragma unroll
    for (int fm = 0; fm < 2; fm++) {
        const int r0g = row0 + wm * 32 + fm * 16 + erow;
        #pragma unroll
        for (int fn = 0; fn < 8; fn++) {
            const int cg = col0 + wn * 64 + fn * 8 + ecol;
            const float b0 = bias[cg], b1 = bias[cg + 1];
            float2 v0 = make_float2(acc[fm][fn][0] + b0, acc[fm][fn][1] + b1);
            float2 v1 = make_float2(acc[fm][fn][2] + b0, acc[fm][fn][3] + b1);
            *reinterpret_cast<float2*>(&C[(size_t)r0g * N + cg]) = v0;
            *reinterpret_cast<float2*>(&C[(size_t)(r0g + 8) * N + cg]) = v1;
        }
    }
}

// ---------------------------------------------------------------------------
// QKV GEMM with fused pack epilogue (all hi-only fp16):
//   Q -> [bh][t][64] (pre-scaled by 1/8);  K -> [bh][t][64];
//   V -> transposed [bh][d][t]
// ---------------------------------------------------------------------------
__global__ __launch_bounds__(GEMM_THREADS) void gemm_qkv(
    const __half* __restrict__ A,
    const __half* __restrict__ B,
    const float* __restrict__ bias,
    __half* __restrict__ qpack,
    __half* __restrict__ kpack,
    __half* __restrict__ vpack)
{
    GEMM_MAINLOOP(A, B)

    const int erow = lane >> 2;
    const int ecol = (lane & 3) << 1;
    const int sec  = col0 >> 10;                      // 0=Q 1=K 2=V
    const int hh   = ((col0 & 1023) >> 6) + wn;       // head (per-warp constant)
    const float scale = (sec == 0) ? 0.125f : 1.0f;

    #pragma unroll
    for (int fm = 0; fm < 2; fm++) {
        const int t0g = row0 + wm * 32 + fm * 16 + erow;
        const int bidx = t0g >> 11;
        const int bh   = bidx * NH + hh;
        const int tl0  = t0g & 2047;
        const int tl1  = tl0 + 8;
        #pragma unroll
        for (int fn = 0; fn < 8; fn++) {
            const int cg = col0 + wn * 64 + fn * 8 + ecol;
            const int d  = (cg & 63);
            const float b0 = bias[cg], b1 = bias[cg + 1];
            const float v00 = (acc[fm][fn][0] + b0) * scale;
            const float v01 = (acc[fm][fn][1] + b1) * scale;
            const float v10 = (acc[fm][fn][2] + b0) * scale;
            const float v11 = (acc[fm][fn][3] + b1) * scale;

            if (sec < 2) {
                __half* dst = (sec == 0) ? qpack : kpack;
                const size_t r0 = ((size_t)bh * TSEQ + tl0) * 64 + d;
                const size_t r1 = ((size_t)bh * TSEQ + tl1) * 64 + d;
                *reinterpret_cast<uint32_t*>(&dst[r0]) = pack_half(v00, v01);
                *reinterpret_cast<uint32_t*>(&dst[r1]) = pack_half(v10, v11);
            } else {
                #pragma unroll
                for (int dd = 0; dd < 2; dd++) {
                    const size_t vb = ((size_t)bh * HD + d + dd) * TSEQ;
                    const float e0 = dd ? v01 : v00;
                    const float e1 = dd ? v11 : v10;
                    vpack[vb + tl0] = __float2half_rn(e0);
                    vpack[vb + tl1] = __float2half_rn(e1);
                }
            }
        }
    }
}

// ---------------------------------------------------------------------------
// Causal flash attention, pure fp16 operands (S = Qhi.Khi, O += Phi.Vhi).
// Tiles: 64 rows x 144B (128B data + 16 pad). smem = 4 tiles = 36.9KB.
// ---------------------------------------------------------------------------
#define TROWB 144
#define TILEB (64 * TROWB)                 // 9216
#define ATTN_SMEM (4 * TILEB)              // 36864 bytes

__global__ __launch_bounds__(128) void attn_mma(
    const __half* __restrict__ qpack,
    const __half* __restrict__ kpack,
    const __half* __restrict__ vpack,
    __half* __restrict__ outp)
{
    extern __shared__ __align__(16) unsigned char smraw[];

    const int qt   = (gridDim.x - 1) - blockIdx.x;
    const int h    = blockIdx.y;
    const int b    = blockIdx.z;
    const int tid  = threadIdx.x;
    const int wid  = tid >> 5;
    const int lane = tid & 31;
    const int q0   = qt * 64;
    const int bh   = b * NH + h;

    const uint32_t KsB = smem_u32(smraw);
    const uint32_t QsB = KsB + TILEB;            // Q staged in K-buf1
    const uint32_t VsB = KsB + 2 * TILEB;

    const __half* qrows = qpack + ((size_t)bh * TSEQ + q0) * 64;
    const __half* krows = kpack + (size_t)bh * TSEQ * 64;
    const __half* vrows = vpack + (size_t)bh * HD * TSEQ;

    auto load_kv = [&](int kt, int buf) {
        const uint32_t kdst = KsB + buf * TILEB;
        const uint32_t vdst = VsB + buf * TILEB;
        #pragma unroll
        for (int i = 0; i < 4; i++) {
            const int idx = i * 128 + tid;      // 512 chunks each
            const int r = idx >> 3;
            const int c = idx & 7;
            CP_ASYNC16(kdst + (uint32_t)(r * TROWB + c * 16),
                       krows + ((size_t)(kt * 64 + r)) * 64 + c * 8);
            CP_ASYNC16(vdst + (uint32_t)(r * TROWB + c * 16),
                       vrows + (size_t)r * TSEQ + kt * 64 + c * 8);
        }
    };

    // Prologue: Q + first K/V tile
    #pragma unroll
    for (int i = 0; i < 4; i++) {
        const int idx = i * 128 + tid;
        const int r = idx >> 3;
        const int c = idx & 7;
        CP_ASYNC16(QsB + (uint32_t)(r * TROWB + c * 16),
                   qrows + (size_t)r * 64 + c * 8);
    }
    load_kv(0, 0);
    CP_COMMIT();
    CP_WAIT(0);
    __syncthreads();

    const int lrow  = lane & 15;
    const int lcolb = (lane >> 4) << 4;
    uint32_t ah[4][4];
    #pragma unroll
    for (int ks = 0; ks < 4; ks++) {
        const uint32_t ad = QsB + (uint32_t)((16 * wid + lrow) * TROWB + ks * 32) + lcolb;
        LDSM_X4(ah[ks][0], ah[ks][1], ah[ks][2], ah[ks][3], ad);
    }
    __syncthreads();   // Q region free before kt=1 prefetch reuses K-buf1

    float oacc[8][4];
    #pragma unroll
    for (int t = 0; t < 8; t++)
        #pragma unroll
        for (int j = 0; j < 4; j++) oacc[t][j] = 0.f;
    float m0r = -1.0e30f, m1r = -1.0e30f, l0 = 0.f, l1 = 0.f;

    const int rl0 = 16 * wid + (lane >> 2);
    const int rl1 = rl0 + 8;

    for (int kt = 0; kt <= qt; kt++) {
        if (kt < qt) { load_kv(kt + 1, (kt + 1) & 1); CP_COMMIT(); }

        const uint32_t kB = KsB + (kt & 1) * TILEB;
        const uint32_t vB = VsB + (kt & 1) * TILEB;

        float sf[8][4];
        #pragma unroll
        for (int t = 0; t < 8; t++)
            #pragma unroll
            for (int j = 0; j < 4; j++) sf[t][j] = 0.f;

        #pragma unroll
        for (int ks = 0; ks < 4; ks++) {
            uint32_t bq[4][4];
            #pragma unroll
            for (int g = 0; g < 4; g++) {
                const uint32_t bd = kB +
                    (uint32_t)((g * 16 + lrow) * TROWB + ks * 32) + lcolb;
                LDSM_X4(bq[g][0], bq[g][1], bq[g][2], bq[g][3], bd);
            }
            #pragma unroll
            for (int g = 0; g < 4; g++)
                #pragma unroll
                for (int hh = 0; hh < 2; hh++) {
                    const int t = 2 * g + hh;
                    MMA_F16(sf[t][0], sf[t][1], sf[t][2], sf[t][3],
                            ah[ks][0], ah[ks][1], ah[ks][2], ah[ks][3],
                            bq[g][hh], bq[g][2 + hh]);
                }
        }

        if (kt == qt) {
            #pragma unroll
            for (int t = 0; t < 8; t++) {
                const int c = t * 8 + 2 * (lane & 3);
                if (c     > rl0) sf[t][0] = -1.0e30f;
                if (c + 1 > rl0) sf[t][1] = -1.0e30f;
                if (c     > rl1) sf[t][2] = -1.0e30f;
                if (c + 1 > rl1) sf[t][3] = -1.0e30f;
            }
        }

        float rm0 = -1.0e30f, rm1 = -1.0e30f;
        #pragma unroll
        for (int t = 0; t < 8; t++) {
            rm0 = fmaxf(rm0, fmaxf(sf[t][0], sf[t][1]));
            rm1 = fmaxf(rm1, fmaxf(sf[t][2], sf[t][3]));
        }
        rm0 = fmaxf(rm0, __shfl_xor_sync(0xffffffffu, rm0, 1));
        rm0 = fmaxf(rm0, __shfl_xor_sync(0xffffffffu, rm0, 2));
        rm1 = fmaxf(rm1, __shfl_xor_sync(0xffffffffu, rm1, 1));
        rm1 = fmaxf(rm1, __shfl_xor_sync(0xffffffffu, rm1, 2));
        const float mn0 = fmaxf(m0r, rm0);
        const float mn1 = fmaxf(m1r, rm1);

        float sum0 = 0.f, sum1 = 0.f;
        #pragma unroll
        for (int t = 0; t < 8; t++) {
            sf[t][0] = __expf(sf[t][0] - mn0);
            sf[t][1] = __expf(sf[t][1] - mn0);
            sf[t][2] = __expf(sf[t][2] - mn1);
            sf[t][3] = __expf(sf[t][3] - mn1);
            sum0 += sf[t][0] + sf[t][1];
            sum1 += sf[t][2] + sf[t][3];
        }
        sum0 += __shfl_xor_sync(0xffffffffu, sum0, 1);
        sum0 += __shfl_xor_sync(0xffffffffu, sum0, 2);
        sum1 += __shfl_xor_sync(0xffffffffu, sum1, 1);
        sum1 += __shfl_xor_sync(0xffffffffu, sum1, 2);

        const float al0 = __expf(m0r - mn0);
        const float al1 = __expf(m1r - mn1);
        l0 = l0 * al0 + sum0;  m0r = mn0;
        l1 = l1 * al1 + sum1;  m1r = mn1;
        #pragma unroll
        for (int t = 0; t < 8; t++) {
            oacc[t][0] *= al0; oacc[t][1] *= al0;
            oacc[t][2] *= al1; oacc[t][3] *= al1;
        }

        uint32_t phi[4][4];
        #pragma unroll
        for (int ks = 0; ks < 4; ks++) {
            const float* e0 = sf[2 * ks];
            const float* e1 = sf[2 * ks + 1];
            phi[ks][0] = pack_half(e0[0], e0[1]);
            phi[ks][1] = pack_half(e0[2], e0[3]);
            phi[ks][2] = pack_half(e1[0], e1[1]);
            phi[ks][3] = pack_half(e1[2], e1[3]);
        }

        #pragma unroll
        for (int ks = 0; ks < 4; ks++) {
            uint32_t bq[4][4];
            #pragma unroll
            for (int g = 0; g < 4; g++) {
                const uint32_t bd = vB +
                    (uint32_t)((g * 16 + lrow) * TROWB + ks * 32) + lcolb;
                LDSM_X4(bq[g][0], bq[g][1], bq[g][2], bq[g][3], bd);
            }
            #pragma unroll
            for (int g = 0; g < 4; g++)
                #pragma unroll
                for (int hh = 0; hh < 2; hh++) {
                    const int t = 2 * g + hh;
                    MMA_F16(oacc[t][0], oacc[t][1], oacc[t][2], oacc[t][3],
                            phi[ks][0], phi[ks][1], phi[ks][2], phi[ks][3],
                            bq[g][hh], bq[g][2 + hh]);
                }
        }

        if (kt < qt) {
            CP_WAIT(0);
            __syncthreads();
        }
    }

    // ---- Epilogue: hi-only fp16 proj input [M, CDIM] ----
    const float inv0 = 1.0f / l0;
    const float inv1 = 1.0f / l1;
    const int r0g = q0 + rl0;
    const int r1g = q0 + rl1;
    const size_t pb0 = ((size_t)b * TSEQ + r0g) * CDIM + h * HD;
    const size_t pb1 = ((size_t)b * TSEQ + r1g) * CDIM + h * HD;
    #pragma unroll
    for (int t = 0; t < 8; t++) {
        const int cg = t * 8 + 2 * (lane & 3);
        *reinterpret_cast<uint32_t*>(&outp[pb0 + cg]) =
            pack_half(oacc[t][0] * inv0, oacc[t][1] * inv0);
        *reinterpret_cast<uint32_t*>(&outp[pb1 + cg]) =
            pack_half(oacc[t][2] * inv1, oacc[t][3] * inv1);
    }
}

// ---------------------------------------------------------------------------
// Launch
// ---------------------------------------------------------------------------
extern "C" void kernel_launch(void* const* d_in, const int* in_sizes, int n_in,
                              void* d_out, int out_size)
{
    const float* x     = (const float*)d_in[0];
    const float* Wqkv  = (const float*)d_in[1];
    const float* bqkv  = (const float*)d_in[2];
    const float* Wproj = (const float*)d_in[3];
    const float* bproj = (const float*)d_in[4];
    float* out = (float*)d_out;

    __half *ahat, *bqkvp, *bprojp, *qp, *kp, *vp;
    cudaGetSymbolAddress((void**)&ahat,   g_ahat);
    cudaGetSymbolAddress((void**)&bqkvp,  g_bqkv);
    cudaGetSymbolAddress((void**)&bprojp, g_bproj);
    cudaGetSymbolAddress((void**)&qp,     g_qpack);
    cudaGetSymbolAddress((void**)&kp,     g_kpack);
    cudaGetSymbolAddress((void**)&vp,     g_vpack);

    cudaFuncSetAttribute(attn_mma,
                         cudaFuncAttributeMaxDynamicSharedMemorySize, ATTN_SMEM);
    cudaFuncSetAttribute(gemm_mma,
                         cudaFuncAttributeMaxDynamicSharedMemorySize, GEMM_SMEM);
    cudaFuncSetAttribute(gemm_qkv,
                         cudaFuncAttributeMaxDynamicSharedMemorySize, GEMM_SMEM);

    // Pack weights -> [N, 2K] fp16 [hi|lo]
    {
        dim3 bb(32, 8);
        convert_split_wT<<<dim3(THREEC / 32, CDIM / 32), bb>>>(Wqkv, bqkvp, CDIM, THREEC);
        convert_split_wT<<<dim3(CDIM / 32, CDIM / 32), bb>>>(Wproj, bprojp, CDIM, CDIM);
    }

    // 1) Pack x (hi-only fp16); QKV GEMM writes packed Q/K/V directly
    {
        const int mk4 = MROWS * CDIM / 4;
        convert_act_f16<<<(mk4 + 255) / 256, 256>>>(
            (const float4*)x, (uint2*)ahat, mk4);
    }
    gemm_qkv<<<dim3(THREEC / 128, MROWS / 128), GEMM_THREADS, GEMM_SMEM>>>(
        ahat, bqkvp, bqkv, qp, kp, vp);

    // 2) Pipelined attention (pure fp16) -> hi-only proj input
    attn_mma<<<dim3(TSEQ / 64, NH, BATCH), 128, ATTN_SMEM>>>(qp, kp, vp, ahat);

    // 3) Output projection
    gemm_mma<<<dim3(CDIM / 128, MROWS / 128), GEMM_THREADS, GEMM_SMEM>>>(
        ahat, bprojp, bproj, out, MROWS, CDIM);
}

// round 16
// speedup vs baseline: 2.5816x; 1.4573x over previous
#include <cuda_runtime.h>
#include <cuda_fp16.h>
#include <math.h>
#include <cstdint>

// Problem constants
#define BATCH 2
#define TSEQ  2048
#define CDIM  1024
#define NH    16
#define HD    64
#define THREEC (3*CDIM)
#define MROWS (BATCH*TSEQ)   // 4096

// ---------------------------------------------------------------------------
// Scratch (__device__ globals; allocation-free rule)
// ---------------------------------------------------------------------------
__device__ __half g_ahat[(size_t)MROWS * CDIM];     // activations fp16
__device__ __half g_bqkv[(size_t)THREEC * CDIM];    // Wqkv^T fp16
__device__ __half g_bproj[(size_t)CDIM * CDIM];     // Wproj^T fp16
// Attention operands (fp16, written by the QKV GEMM epilogue)
__device__ __half g_qpack[(size_t)BATCH * NH * TSEQ * 64];   // [bh][t][d]
__device__ __half g_kpack[(size_t)BATCH * NH * TSEQ * 64];   // [bh][t][d]
__device__ __half g_vpack[(size_t)BATCH * NH * HD * TSEQ];   // [bh][d][t]

// ---------------------------------------------------------------------------
// Helpers (base-ISA only: cp.async / ldmatrix / mma.sync)
// ---------------------------------------------------------------------------
__device__ __forceinline__ uint32_t smem_u32(const void* p) {
    uint32_t a;
    asm("{ .reg .u64 t; cvta.to.shared.u64 t, %1; cvt.u32.u64 %0, t; }"
        : "=r"(a) : "l"(p));
    return a;
}
#define CP_ASYNC16(smaddr, gptr) \
    asm volatile("cp.async.cg.shared.global [%0], [%1], 16;" \
                 :: "r"(smaddr), "l"(gptr))
#define CP_COMMIT() asm volatile("cp.async.commit_group;" ::: "memory")
#define CP_WAIT(n)  asm volatile("cp.async.wait_group %0;" :: "n"(n) : "memory")

#define LDSM_X4(r0, r1, r2, r3, addr) \
    asm volatile("ldmatrix.sync.aligned.m8n8.x4.shared.b16 {%0,%1,%2,%3}, [%4];" \
                 : "=r"(r0), "=r"(r1), "=r"(r2), "=r"(r3) : "r"(addr))

#define MMA_F16(c0, c1, c2, c3, a0, a1, a2, a3, b0, b1) \
    asm volatile("mma.sync.aligned.m16n8k16.row.col.f32.f16.f16.f32 " \
                 "{%0,%1,%2,%3}, {%4,%5,%6,%7}, {%8,%9}, {%0,%1,%2,%3};" \
                 : "+f"(c0), "+f"(c1), "+f"(c2), "+f"(c3) \
                 : "r"(a0), "r"(a1), "r"(a2), "r"(a3), "r"(b0), "r"(b1))

__device__ __forceinline__ uint32_t pack_half(float x, float y) {
    __half2 h = __floats2half2_rn(x, y);
    return *reinterpret_cast<uint32_t*>(&h);
}

// ---------------------------------------------------------------------------
// Convert activations: A[M,K] fp32 -> fp16, vectorized.
// ---------------------------------------------------------------------------
__global__ void convert_act_f16(const float4* __restrict__ in,
                                uint2* __restrict__ out, int MK4)
{
    const int idx = blockIdx.x * blockDim.x + threadIdx.x;
    if (idx >= MK4) return;
    const float4 v = in[idx];
    out[idx] = make_uint2(pack_half(v.x, v.y), pack_half(v.z, v.w));
}

// ---------------------------------------------------------------------------
// Transpose weights: W[K,N] fp32 -> Bhat[N,K] fp16
// ---------------------------------------------------------------------------
__global__ void convert_wT_f16(const float* __restrict__ W,
                               __half* __restrict__ out, int K, int N)
{
    __shared__ float t[32][33];
    const int tx = threadIdx.x, ty = threadIdx.y;   // block (32, 8)
    const int n0 = blockIdx.x * 32, k0 = blockIdx.y * 32;
    #pragma unroll
    for (int j = 0; j < 4; j++)
        t[ty + j * 8][tx] = W[(size_t)(k0 + ty + j * 8) * N + n0 + tx];
    __syncthreads();
    #pragma unroll
    for (int j = 0; j < 4; j++) {
        const int nn = ty + j * 8;
        out[(size_t)(n0 + nn) * K + k0 + tx] = __float2half_rn(t[tx][nn]);
    }
}

// ---------------------------------------------------------------------------
// GEMM: 128x128 CTA tile, 8 warps (256 thr), 32x64 warp tile, pure fp16.
// A [M, CDIM], B [N, CDIM] (row-major, K-contiguous).
// ---------------------------------------------------------------------------
#define GBK   32
#define NSTG  (CDIM / GBK)            // 32
#define ROWB  80                      // 64B data + 16 pad
#define STAGE_T (128 * ROWB)          // 10240 per matrix per stage
#define STAGES 2
#define GEMM_SMEM (2 * STAGES * STAGE_T)   // 40960
#define GEMM_THREADS 256

#define GEMM_MAINLOOP(Aptr, Bptr)                                              \
    extern __shared__ __align__(16) unsigned char gsm[];                       \
    const int tid  = threadIdx.x;                                              \
    const int wid  = tid >> 5;                                                 \
    const int lane = tid & 31;                                                 \
    const int wm   = wid & 3;                                                  \
    const int wn   = wid >> 2;                                                 \
    const int row0 = blockIdx.y * 128;                                         \
    const int col0 = blockIdx.x * 128;                                         \
    const uint32_t smA_b = smem_u32(gsm);                                      \
    const uint32_t smB_b = smA_b + STAGES * STAGE_T;                           \
    const __half* Arow = (Aptr) + (size_t)row0 * CDIM;                         \
    const __half* Brow = (Bptr) + (size_t)col0 * CDIM;                         \
    auto load_stage = [&](int s, int buf) {                                    \
        const int k0 = s * GBK;                                                \
        const uint32_t ao = smA_b + buf * STAGE_T;                             \
        const uint32_t bo = smB_b + buf * STAGE_T;                             \
        _Pragma("unroll")                                                      \
        for (int i = 0; i < 2; i++) {                                          \
            const int idx = i * 256 + tid;       /* 512 chunks each */         \
            const int r = idx >> 2, c = idx & 3;                               \
            const uint32_t so = (uint32_t)(r * ROWB + c * 16);                 \
            CP_ASYNC16(ao + so, Arow + (size_t)r * CDIM + k0 + c * 8);         \
            CP_ASYNC16(bo + so, Brow + (size_t)r * CDIM + k0 + c * 8);         \
        }                                                                      \
    };                                                                         \
    float acc[2][8][4];                                                        \
    _Pragma("unroll")                                                          \
    for (int i = 0; i < 2; i++)                                                \
        _Pragma("unroll")                                                      \
        for (int j = 0; j < 8; j++)                                            \
            _Pragma("unroll")                                                  \
            for (int k = 0; k < 4; k++) acc[i][j][k] = 0.f;                    \
    const int lrow = lane & 15;                                                \
    const int lcol = (lane >> 4) << 4;                                         \
    load_stage(0, 0);                                                          \
    CP_COMMIT();                                                               \
    for (int s = 0; s < NSTG; s++) {                                           \
        CP_WAIT(0);                                                            \
        __syncthreads();                                                       \
        if (s + 1 < NSTG) { load_stage(s + 1, (s + 1) & 1); CP_COMMIT(); }     \
        const int buf = s & 1;                                                 \
        const uint32_t aB = smA_b + buf * STAGE_T;                             \
        const uint32_t bB = smB_b + buf * STAGE_T;                             \
        _Pragma("unroll")                                                      \
        for (int ks = 0; ks < 2; ks++) {                                       \
            uint32_t ah[2][4], bq[4][4];                                       \
            _Pragma("unroll")                                                  \
            for (int fm = 0; fm < 2; fm++) {                                   \
                const uint32_t ad = aB +                                       \
                    (uint32_t)((wm * 32 + fm * 16 + lrow) * ROWB + ks * 32) + lcol; \
                LDSM_X4(ah[fm][0], ah[fm][1], ah[fm][2], ah[fm][3], ad);       \
            }                                                                  \
            _Pragma("unroll")                                                  \
            for (int g = 0; g < 4; g++) {                                      \
                const uint32_t bd = bB +                                       \
                    (uint32_t)((wn * 64 + g * 16 + lrow) * ROWB + ks * 32) + lcol; \
                LDSM_X4(bq[g][0], bq[g][1], bq[g][2], bq[g][3], bd);           \
            }                                                                  \
            _Pragma("unroll")                                                  \
            for (int fm = 0; fm < 2; fm++)                                     \
                _Pragma("unroll")                                              \
                for (int fn = 0; fn < 8; fn++) {                               \
                    const int g = fn >> 1, h = fn & 1;                         \
                    MMA_F16(acc[fm][fn][0], acc[fm][fn][1],                    \
                            acc[fm][fn][2], acc[fm][fn][3],                    \
                            ah[fm][0], ah[fm][1], ah[fm][2], ah[fm][3],        \
                            bq[g][h], bq[g][2 + h]);                           \
                }                                                              \
        }                                                                      \
    }

// ---------------------------------------------------------------------------
// Proj GEMM: plain fp32 output + bias
// ---------------------------------------------------------------------------
__global__ __launch_bounds__(GEMM_THREADS) void gemm_mma(
    const __half* __restrict__ A,
    const __half* __restrict__ B,
    const float* __restrict__ bias,
    float* __restrict__ C, int M, int N)
{
    GEMM_MAINLOOP(A, B)

    const int erow = lane >> 2;
    const int ecol = (lane & 3) << 1;
    #pragma unroll
    for (int fm = 0; fm < 2; fm++) {
        const int r0g = row0 + wm * 32 + fm * 16 + erow;
        #pragma unroll
        for (int fn = 0; fn < 8; fn++) {
            const int cg = col0 + wn * 64 + fn * 8 + ecol;
            const float b0 = bias[cg], b1 = bias[cg + 1];
            float2 v0 = make_float2(acc[fm][fn][0] + b0, acc[fm][fn][1] + b1);
            float2 v1 = make_float2(acc[fm][fn][2] + b0, acc[fm][fn][3] + b1);
            *reinterpret_cast<float2*>(&C[(size_t)r0g * N + cg]) = v0;
            *reinterpret_cast<float2*>(&C[(size_t)(r0g + 8) * N + cg]) = v1;
        }
    }
}

// ---------------------------------------------------------------------------
// QKV GEMM with fused pack epilogue (all fp16):
//   Q -> [bh][t][64] (pre-scaled by 1/8);  K -> [bh][t][64];
//   V -> transposed [bh][d][t]
// ---------------------------------------------------------------------------
__global__ __launch_bounds__(GEMM_THREADS) void gemm_qkv(
    const __half* __restrict__ A,
    const __half* __restrict__ B,
    const float* __restrict__ bias,
    __half* __restrict__ qpack,
    __half* __restrict__ kpack,
    __half* __restrict__ vpack)
{
    GEMM_MAINLOOP(A, B)

    const int erow = lane >> 2;
    const int ecol = (lane & 3) << 1;
    const int sec  = col0 >> 10;                      // 0=Q 1=K 2=V
    const int hh   = ((col0 & 1023) >> 6) + wn;       // head (per-warp constant)
    const float scale = (sec == 0) ? 0.125f : 1.0f;

    #pragma unroll
    for (int fm = 0; fm < 2; fm++) {
        const int t0g = row0 + wm * 32 + fm * 16 + erow;
        const int bidx = t0g >> 11;
        const int bh   = bidx * NH + hh;
        const int tl0  = t0g & 2047;
        const int tl1  = tl0 + 8;
        #pragma unroll
        for (int fn = 0; fn < 8; fn++) {
            const int cg = col0 + wn * 64 + fn * 8 + ecol;
            const int d  = (cg & 63);
            const float b0 = bias[cg], b1 = bias[cg + 1];
            const float v00 = (acc[fm][fn][0] + b0) * scale;
            const float v01 = (acc[fm][fn][1] + b1) * scale;
            const float v10 = (acc[fm][fn][2] + b0) * scale;
            const float v11 = (acc[fm][fn][3] + b1) * scale;

            if (sec < 2) {
                __half* dst = (sec == 0) ? qpack : kpack;
                const size_t r0 = ((size_t)bh * TSEQ + tl0) * 64 + d;
                const size_t r1 = ((size_t)bh * TSEQ + tl1) * 64 + d;
                *reinterpret_cast<uint32_t*>(&dst[r0]) = pack_half(v00, v01);
                *reinterpret_cast<uint32_t*>(&dst[r1]) = pack_half(v10, v11);
            } else {
                #pragma unroll
                for (int dd = 0; dd < 2; dd++) {
                    const size_t vb = ((size_t)bh * HD + d + dd) * TSEQ;
                    const float e0 = dd ? v01 : v00;
                    const float e1 = dd ? v11 : v10;
                    vpack[vb + tl0] = __float2half_rn(e0);
                    vpack[vb + tl1] = __float2half_rn(e1);
                }
            }
        }
    }
}

// ---------------------------------------------------------------------------
// Causal flash attention, pure fp16 operands (unchanged from R15 — verified).
// ---------------------------------------------------------------------------
#define TROWB 144
#define TILEB (64 * TROWB)                 // 9216
#define ATTN_SMEM (4 * TILEB)              // 36864 bytes

__global__ __launch_bounds__(128) void attn_mma(
    const __half* __restrict__ qpack,
    const __half* __restrict__ kpack,
    const __half* __restrict__ vpack,
    __half* __restrict__ outp)
{
    extern __shared__ __align__(16) unsigned char smraw[];

    const int qt   = (gridDim.x - 1) - blockIdx.x;
    const int h    = blockIdx.y;
    const int b    = blockIdx.z;
    const int tid  = threadIdx.x;
    const int wid  = tid >> 5;
    const int lane = tid & 31;
    const int q0   = qt * 64;
    const int bh   = b * NH + h;

    const uint32_t KsB = smem_u32(smraw);
    const uint32_t QsB = KsB + TILEB;            // Q staged in K-buf1
    const uint32_t VsB = KsB + 2 * TILEB;

    const __half* qrows = qpack + ((size_t)bh * TSEQ + q0) * 64;
    const __half* krows = kpack + (size_t)bh * TSEQ * 64;
    const __half* vrows = vpack + (size_t)bh * HD * TSEQ;

    auto load_kv = [&](int kt, int buf) {
        const uint32_t kdst = KsB + buf * TILEB;
        const uint32_t vdst = VsB + buf * TILEB;
        #pragma unroll
        for (int i = 0; i < 4; i++) {
            const int idx = i * 128 + tid;
            const int r = idx >> 3;
            const int c = idx & 7;
            CP_ASYNC16(kdst + (uint32_t)(r * TROWB + c * 16),
                       krows + ((size_t)(kt * 64 + r)) * 64 + c * 8);
            CP_ASYNC16(vdst + (uint32_t)(r * TROWB + c * 16),
                       vrows + (size_t)r * TSEQ + kt * 64 + c * 8);
        }
    };

    #pragma unroll
    for (int i = 0; i < 4; i++) {
        const int idx = i * 128 + tid;
        const int r = idx >> 3;
        const int c = idx & 7;
        CP_ASYNC16(QsB + (uint32_t)(r * TROWB + c * 16),
                   qrows + (size_t)r * 64 + c * 8);
    }
    load_kv(0, 0);
    CP_COMMIT();
    CP_WAIT(0);
    __syncthreads();

    const int lrow  = lane & 15;
    const int lcolb = (lane >> 4) << 4;
    uint32_t ah[4][4];
    #pragma unroll
    for (int ks = 0; ks < 4; ks++) {
        const uint32_t ad = QsB + (uint32_t)((16 * wid + lrow) * TROWB + ks * 32) + lcolb;
        LDSM_X4(ah[ks][0], ah[ks][1], ah[ks][2], ah[ks][3], ad);
    }
    __syncthreads();

    float oacc[8][4];
    #pragma unroll
    for (int t = 0; t < 8; t++)
        #pragma unroll
        for (int j = 0; j < 4; j++) oacc[t][j] = 0.f;
    float m0r = -1.0e30f, m1r = -1.0e30f, l0 = 0.f, l1 = 0.f;

    const int rl0 = 16 * wid + (lane >> 2);
    const int rl1 = rl0 + 8;

    for (int kt = 0; kt <= qt; kt++) {
        if (kt < qt) { load_kv(kt + 1, (kt + 1) & 1); CP_COMMIT(); }

        const uint32_t kB = KsB + (kt & 1) * TILEB;
        const uint32_t vB = VsB + (kt & 1) * TILEB;

        float sf[8][4];
        #pragma unroll
        for (int t = 0; t < 8; t++)
            #pragma unroll
            for (int j = 0; j < 4; j++) sf[t][j] = 0.f;

        #pragma unroll
        for (int ks = 0; ks < 4; ks++) {
            uint32_t bq[4][4];
            #pragma unroll
            for (int g = 0; g < 4; g++) {
                const uint32_t bd = kB +
                    (uint32_t)((g * 16 + lrow) * TROWB + ks * 32) + lcolb;
                LDSM_X4(bq[g][0], bq[g][1], bq[g][2], bq[g][3], bd);
            }
            #pragma unroll
            for (int g = 0; g < 4; g++)
                #pragma unroll
                for (int hh = 0; hh < 2; hh++) {
                    const int t = 2 * g + hh;
                    MMA_F16(sf[t][0], sf[t][1], sf[t][2], sf[t][3],
                            ah[ks][0], ah[ks][1], ah[ks][2], ah[ks][3],
                            bq[g][hh], bq[g][2 + hh]);
                }
        }

        if (kt == qt) {
            #pragma unroll
            for (int t = 0; t < 8; t++) {
                const int c = t * 8 + 2 * (lane & 3);
                if (c     > rl0) sf[t][0] = -1.0e30f;
                if (c + 1 > rl0) sf[t][1] = -1.0e30f;
                if (c     > rl1) sf[t][2] = -1.0e30f;
                if (c + 1 > rl1) sf[t][3] = -1.0e30f;
            }
        }

        float rm0 = -1.0e30f, rm1 = -1.0e30f;
        #pragma unroll
        for (int t = 0; t < 8; t++) {
            rm0 = fmaxf(rm0, fmaxf(sf[t][0], sf[t][1]));
            rm1 = fmaxf(rm1, fmaxf(sf[t][2], sf[t][3]));
        }
        rm0 = fmaxf(rm0, __shfl_xor_sync(0xffffffffu, rm0, 1));
        rm0 = fmaxf(rm0, __shfl_xor_sync(0xffffffffu, rm0, 2));
        rm1 = fmaxf(rm1, __shfl_xor_sync(0xffffffffu, rm1, 1));
        rm1 = fmaxf(rm1, __shfl_xor_sync(0xffffffffu, rm1, 2));
        const float mn0 = fmaxf(m0r, rm0);
        const float mn1 = fmaxf(m1r, rm1);

        float sum0 = 0.f, sum1 = 0.f;
        #pragma unroll
        for (int t = 0; t < 8; t++) {
            sf[t][0] = __expf(sf[t][0] - mn0);
            sf[t][1] = __expf(sf[t][1] - mn0);
            sf[t][2] = __expf(sf[t][2] - mn1);
            sf[t][3] = __expf(sf[t][3] - mn1);
            sum0 += sf[t][0] + sf[t][1];
            sum1 += sf[t][2] + sf[t][3];
        }
        sum0 += __shfl_xor_sync(0xffffffffu, sum0, 1);
        sum0 += __shfl_xor_sync(0xffffffffu, sum0, 2);
        sum1 += __shfl_xor_sync(0xffffffffu, sum1, 1);
        sum1 += __shfl_xor_sync(0xffffffffu, sum1, 2);

        const float al0 = __expf(m0r - mn0);
        const float al1 = __expf(m1r - mn1);
        l0 = l0 * al0 + sum0;  m0r = mn0;
        l1 = l1 * al1 + sum1;  m1r = mn1;
        #pragma unroll
        for (int t = 0; t < 8; t++) {
            oacc[t][0] *= al0; oacc[t][1] *= al0;
            oacc[t][2] *= al1; oacc[t][3] *= al1;
        }

        uint32_t phi[4][4];
        #pragma unroll
        for (int ks = 0; ks < 4; ks++) {
            const float* e0 = sf[2 * ks];
            const float* e1 = sf[2 * ks + 1];
            phi[ks][0] = pack_half(e0[0], e0[1]);
            phi[ks][1] = pack_half(e0[2], e0[3]);
            phi[ks][2] = pack_half(e1[0], e1[1]);
            phi[ks][3] = pack_half(e1[2], e1[3]);
        }

        #pragma unroll
        for (int ks = 0; ks < 4; ks++) {
            uint32_t bq[4][4];
            #pragma unroll
            for (int g = 0; g < 4; g++) {
                const uint32_t bd = vB +
                    (uint32_t)((g * 16 + lrow) * TROWB + ks * 32) + lcolb;
                LDSM_X4(bq[g][0], bq[g][1], bq[g][2], bq[g][3], bd);
            }
            #pragma unroll
            for (int g = 0; g < 4; g++)
                #pragma unroll
                for (int hh = 0; hh < 2; hh++) {
                    const int t = 2 * g + hh;
                    MMA_F16(oacc[t][0], oacc[t][1], oacc[t][2], oacc[t][3],
                            phi[ks][0], phi[ks][1], phi[ks][2], phi[ks][3],
                            bq[g][hh], bq[g][2 + hh]);
                }
        }

        if (kt < qt) {
            CP_WAIT(0);
            __syncthreads();
        }
    }

    // ---- Epilogue: fp16 proj input [M, CDIM] ----
    const float inv0 = 1.0f / l0;
    const float inv1 = 1.0f / l1;
    const int r0g = q0 + rl0;
    const int r1g = q0 + rl1;
    const size_t pb0 = ((size_t)b * TSEQ + r0g) * CDIM + h * HD;
    const size_t pb1 = ((size_t)b * TSEQ + r1g) * CDIM + h * HD;
    #pragma unroll
    for (int t = 0; t < 8; t++) {
        const int cg = t * 8 + 2 * (lane & 3);
        *reinterpret_cast<uint32_t*>(&outp[pb0 + cg]) =
            pack_half(oacc[t][0] * inv0, oacc[t][1] * inv0);
        *reinterpret_cast<uint32_t*>(&outp[pb1 + cg]) =
            pack_half(oacc[t][2] * inv1, oacc[t][3] * inv1);
    }
}

// ---------------------------------------------------------------------------
// Launch
// ---------------------------------------------------------------------------
extern "C" void kernel_launch(void* const* d_in, const int* in_sizes, int n_in,
                              void* d_out, int out_size)
{
    const float* x     = (const float*)d_in[0];
    const float* Wqkv  = (const float*)d_in[1];
    const float* bqkv  = (const float*)d_in[2];
    const float* Wproj = (const float*)d_in[3];
    const float* bproj = (const float*)d_in[4];
    float* out = (float*)d_out;

    __half *ahat, *bqkvp, *bprojp, *qp, *kp, *vp;
    cudaGetSymbolAddress((void**)&ahat,   g_ahat);
    cudaGetSymbolAddress((void**)&bqkvp,  g_bqkv);
    cudaGetSymbolAddress((void**)&bprojp, g_bproj);
    cudaGetSymbolAddress((void**)&qp,     g_qpack);
    cudaGetSymbolAddress((void**)&kp,     g_kpack);
    cudaGetSymbolAddress((void**)&vp,     g_vpack);

    cudaFuncSetAttribute(attn_mma,
                         cudaFuncAttributeMaxDynamicSharedMemorySize, ATTN_SMEM);
    cudaFuncSetAttribute(gemm_mma,
                         cudaFuncAttributeMaxDynamicSharedMemorySize, GEMM_SMEM);
    cudaFuncSetAttribute(gemm_qkv,
                         cudaFuncAttributeMaxDynamicSharedMemorySize, GEMM_SMEM);

    // Pack weights -> [N, K] fp16
    {
        dim3 bb(32, 8);
        convert_wT_f16<<<dim3(THREEC / 32, CDIM / 32), bb>>>(Wqkv, bqkvp, CDIM, THREEC);
        convert_wT_f16<<<dim3(CDIM / 32, CDIM / 32), bb>>>(Wproj, bprojp, CDIM, CDIM);
    }

    // 1) Pack x (fp16); QKV GEMM writes packed Q/K/V directly
    {
        const int mk4 = MROWS * CDIM / 4;
        convert_act_f16<<<(mk4 + 255) / 256, 256>>>(
            (const float4*)x, (uint2*)ahat, mk4);
    }
    gemm_qkv<<<dim3(THREEC / 128, MROWS / 128), GEMM_THREADS, GEMM_SMEM>>>(
        ahat, bqkvp, bqkv, qp, kp, vp);

    // 2) Pipelined attention (pure fp16) -> fp16 proj input
    attn_mma<<<dim3(TSEQ / 64, NH, BATCH), 128, ATTN_SMEM>>>(qp, kp, vp, ahat);

    // 3) Output projection
    gemm_mma<<<dim3(CDIM / 128, MROWS / 128), GEMM_THREADS, GEMM_SMEM>>>(
        ahat, bprojp, bproj, out, MROWS, CDIM);
}